// round 9
// baseline (speedup 1.0000x reference)
#include <cuda_runtime.h>
#include <cuda_fp16.h>
#include <cstdint>
#include <stdint.h>
#include <math.h>

// ---------------- problem constants ----------------
#define BATCH 2
#define CC    128
#define HWSZ  16384         // 128*128
#define HS    64
#define DGRP  8
#define CG    16
#define KPTS  9
#define OMCH  216           // DG*3*KK
#define KBIG  1152          // CC*9

// ---------------- scratch ----------------
__device__ float g_pooled[BATCH * CC];
__device__ float g_scale [BATCH * CC];
__device__ float g_cat   [(size_t)BATCH * 2 * CC * HWSZ];     // fp32: rows 0..127 feat_arm, 128..255 feat_up
__device__ float g_om    [(size_t)BATCH * OMCH * HWSZ];       // fp32 offsets/mask

__device__ __align__(16) __half g_armWh[BATCH * CC * CC];     // fp16 A matrices
__device__ __align__(16) __half g_offwh[CC * 2 * CC];
__device__ __align__(16) __half g_omwh [OMCH * KBIG];
__device__ __align__(16) __half g_dcnwh[CC * KBIG];

// fp16 B operands, k-pair-interleaved word layout: word[kp][n] = (half(2kp,n), half(2kp+1,n))
__device__ __align__(16) __half g_flh  [(size_t)BATCH * CC * HWSZ];       // feat_l
__device__ __align__(16) __half g_cath [(size_t)BATCH * 2 * CC * HWSZ];   // [feat_arm; feat_up]
__device__ __align__(16) __half g_Sh   [(size_t)BATCH * KBIG * HWSZ];     // sampled DCN input
// THREE pre-shifted fp16 copies of off_feat: copy ci (dx=ci-1): copy[ci][b][c][h][x] = off[b][c][h][x+dx]
__device__ __align__(16) __half g_offh3[(size_t)3 * BATCH * CC * HWSZ];

// ---------------- small kernels ----------------
__global__ void pool_kernel(const float* __restrict__ x) {
    int bc = blockIdx.x;
    const float4* p = (const float4*)(x + (size_t)bc * HWSZ);
    float s = 0.f;
    for (int i = threadIdx.x; i < HWSZ / 4; i += 256) {
        float4 v = p[i];
        s += v.x + v.y + v.z + v.w;
    }
    __shared__ float sh[256];
    sh[threadIdx.x] = s;
    __syncthreads();
    for (int o = 128; o > 0; o >>= 1) {
        if (threadIdx.x < o) sh[threadIdx.x] += sh[threadIdx.x + o];
        __syncthreads();
    }
    if (threadIdx.x == 0) g_pooled[bc] = sh[0] * (1.0f / HWSZ);
}

__global__ void atten_kernel(const float* __restrict__ aw, const float* __restrict__ ab,
                             const float* __restrict__ bg, const float* __restrict__ bb,
                             const float* __restrict__ bm, const float* __restrict__ bv) {
    int t = threadIdx.x;
    int b = t >> 7, o = t & 127;
    float a = ab[o];
    const float* pr = g_pooled + b * CC;
    const float* wr = aw + o * CC;
    #pragma unroll 4
    for (int c = 0; c < CC; c++) a += pr[c] * wr[c];
    a = (a - bm[o]) * rsqrtf(bv[o] + 1e-5f) * bg[o] + bb[o];
    g_scale[t] = 1.f + 1.f / (1.f + expf(-a));
}

__global__ void armw_kernel(const float* __restrict__ fsm_w) {
    int i = blockIdx.x * blockDim.x + threadIdx.x;
    int c = i & 127;
    int bo = i >> 7;
    int o = bo & 127;
    int b = bo >> 7;
    g_armWh[i] = __float2half(fsm_w[o * CC + c] * g_scale[b * CC + c]);
}

// weight packing + zero the never-written edge columns of g_offh3
__global__ void whpack_kernel(const float* __restrict__ om_w,
                              const float* __restrict__ dcn_w,
                              const float* __restrict__ off_w) {
    int i = blockIdx.x * blockDim.x + threadIdx.x;
    if (i < OMCH * KBIG) g_omwh[i] = __float2half(om_w[i]);
    if (i < CC * KBIG)   g_dcnwh[i] = __float2half(dcn_w[i]);
    if (i < CC * 2 * CC) g_offwh[i] = __float2half(off_w[i]);
    if (i < 2 * BATCH * CC * 128) {
        int e = i & 1;            // 0 -> copy 0 (dx=-1) x=0 ; 1 -> copy 2 (dx=+1) x=127
        int t = i >> 1;
        int h = t & 127; t >>= 7;
        int c = t & 127; t >>= 7;
        int b = t & 1;
        int ci = e ? 2 : 0;
        int x  = e ? 127 : 0;
        g_offh3[(((size_t)ci * BATCH + b) * CC + c) * HWSZ + h * 128 + x] = __float2half(0.f);
    }
}

// fused: feat_l fp32->fp16 interleaved  AND  upsample feat_s (fp32 + fp16 interleaved)
__global__ void prep_kernel(const float* __restrict__ fl, const float* __restrict__ fs) {
    int i = blockIdx.x * blockDim.x + threadIdx.x;
    if (i >= BATCH * CC * HWSZ) return;
    int n = i & (HWSZ - 1);
    int bc = i >> 14;
    int b = bc >> 7, c = bc & 127;
    g_flh[((size_t)b * (CC / 2) + (c >> 1)) * (2 * HWSZ) + n * 2 + (c & 1)] = __float2half(fl[i]);
    int h = n >> 7, w = n & 127;
    float fy = (h * 63.0f) / 127.0f;
    float fx = (w * 63.0f) / 127.0f;
    int y0 = (int)floorf(fy); float wy = fy - y0; int y1 = min(y0 + 1, 63);
    int x0 = (int)floorf(fx); float wx = fx - x0; int x1 = min(x0 + 1, 63);
    const float* p = fs + (size_t)bc * (HS * HS);
    float v = p[y0 * HS + x0] * (1.f - wy) * (1.f - wx)
            + p[y0 * HS + x1] * (1.f - wy) * wx
            + p[y1 * HS + x0] * wy * (1.f - wx)
            + p[y1 * HS + x1] * wy * wx;
    g_cat[((size_t)b * 2 * CC + CC + c) * HWSZ + n] = v;
    g_cath[((size_t)b * CC + (CC >> 1) + (c >> 1)) * (2 * HWSZ) + n * 2 + (c & 1)] = __float2half(v);
}

// bilinear sample + mask -> fp16 interleaved g_Sh ; corners read as fp16 channel-pair words
__global__ void sample_kernel() {
    int i = blockIdx.x * blockDim.x + threadIdx.x;
    if (i >= BATCH * DGRP * KPTS * HWSZ) return;
    int n = i & (HWSZ - 1);
    int t = i >> 14;
    int k = t % KPTS; t /= KPTS;
    int g = t & 7;
    int b = t >> 3;
    int h = n >> 7, w = n & 127;

    const float* om = g_om + (size_t)b * OMCH * HWSZ;
    int gk = g * KPTS + k;
    float offy = om[(size_t)gk * HWSZ + n];
    float offx = om[(size_t)(72 + gk) * HWSZ + n];
    float mm   = om[(size_t)(144 + gk) * HWSZ + n];
    mm = 1.f / (1.f + expf(-mm));

    float py = (float)(h + k / 3 - 1) + offy;
    float px = (float)(w + k % 3 - 1) + offx;
    float y0f = floorf(py), x0f = floorf(px);
    float ly = py - y0f, lx = px - x0f;
    int y0 = (int)y0f, x0 = (int)x0f;
    int y1 = y0 + 1, x1 = x0 + 1;
    bool vy0 = (y0 >= 0 && y0 < 128), vy1 = (y1 >= 0 && y1 < 128);
    bool vx0 = (x0 >= 0 && x0 < 128), vx1 = (x1 >= 0 && x1 < 128);
    int cy0 = min(max(y0, 0), 127), cy1 = min(max(y1, 0), 127);
    int cx0 = min(max(x0, 0), 127), cx1 = min(max(x1, 0), 127);
    float w00 = (vy0 && vx0) ? (1.f - ly) * (1.f - lx) * mm : 0.f;
    float w01 = (vy0 && vx1) ? (1.f - ly) * lx * mm : 0.f;
    float w10 = (vy1 && vx0) ? ly * (1.f - lx) * mm : 0.f;
    float w11 = (vy1 && vx1) ? ly * lx * mm : 0.f;
    int i00 = (cy0 << 7) + cx0, i01 = (cy0 << 7) + cx1;
    int i10 = (cy1 << 7) + cx0, i11 = (cy1 << 7) + cx1;

    const unsigned int* cw = (const unsigned int*)g_cath + (size_t)b * CC * HWSZ;
    #pragma unroll
    for (int cp = 0; cp < 8; cp++) {
        const unsigned int* rowp = cw + (size_t)(64 + g * 8 + cp) * HWSZ;
        float2 c00 = __half22float2(*(const __half2*)&rowp[i00]);
        float2 c01 = __half22float2(*(const __half2*)&rowp[i01]);
        float2 c10 = __half22float2(*(const __half2*)&rowp[i10]);
        float2 c11 = __half22float2(*(const __half2*)&rowp[i11]);
        float ve = w00 * c00.x + w01 * c01.x + w10 * c10.x + w11 * c11.x;
        float vo = w00 * c00.y + w01 * c01.y + w10 * c10.y + w11 * c11.y;
        int re = g * 144 + (2 * cp) * 9 + k;
        int ro = re + 9;
        g_Sh[((size_t)b * (KBIG / 2) + (re >> 1)) * (2 * HWSZ) + n * 2 + (re & 1)] = __float2half(ve);
        g_Sh[((size_t)b * (KBIG / 2) + (ro >> 1)) * (2 * HWSZ) + n * 2 + (ro & 1)] = __float2half(vo);
    }
}

// ---------------- FP16 tensor-core GEMM ----------------
// BM=BN=128, BK=32 halves, 256 threads, 8 warps 2x4, m16n8k16,
// 3-stage cp.async pipeline, ONE __syncthreads per k-iteration, dynamic smem.
#define AHSTR 40   // halves per A smem row; word stride 20
#define BWSTR 136  // words per B kp-row
#define A_STG (128 * AHSTR)          // halves per A stage
#define B_STG (16 * BWSTR)           // words per B stage
#define SMEM_BYTES (3 * (A_STG * 2 + B_STG * 4))   // 56832

#define HGEMM_CORE()                                                                        \
    {                                                                                       \
    const unsigned int* aw = (const unsigned int*)(Asm + (size_t)cur * A_STG);              \
    const unsigned int* bw = Bsm + (size_t)cur * B_STG;                                     \
    _Pragma("unroll")                                                                       \
    for (int ks = 0; ks < 2; ks++) {                                                        \
        unsigned int af[4][4], bf[4][2];                                                    \
        _Pragma("unroll")                                                                   \
        for (int mi = 0; mi < 4; mi++) {                                                    \
            int row = wm + mi * 16 + gid;                                                   \
            af[mi][0] = aw[row * 20 + ks * 8 + tig];                                        \
            af[mi][1] = aw[(row + 8) * 20 + ks * 8 + tig];                                  \
            af[mi][2] = aw[row * 20 + ks * 8 + tig + 4];                                    \
            af[mi][3] = aw[(row + 8) * 20 + ks * 8 + tig + 4];                              \
        }                                                                                   \
        _Pragma("unroll")                                                                   \
        for (int ni = 0; ni < 4; ni++) {                                                    \
            int col = wn + ni * 8 + gid;                                                    \
            bf[ni][0] = bw[(ks * 8 + tig) * BWSTR + col];                                   \
            bf[ni][1] = bw[(ks * 8 + tig + 4) * BWSTR + col];                               \
        }                                                                                   \
        _Pragma("unroll")                                                                   \
        for (int mi = 0; mi < 4; mi++)                                                      \
            _Pragma("unroll")                                                               \
            for (int ni = 0; ni < 4; ni++) {                                                \
                asm volatile(                                                               \
                    "mma.sync.aligned.m16n8k16.row.col.f32.f16.f16.f32 "                    \
                    "{%0,%1,%2,%3}, {%4,%5,%6,%7}, {%8,%9}, {%0,%1,%2,%3};\n"               \
                    : "+f"(acc[mi][ni][0]), "+f"(acc[mi][ni][1]),                           \
                      "+f"(acc[mi][ni][2]), "+f"(acc[mi][ni][3])                            \
                    : "r"(af[mi][0]), "r"(af[mi][1]), "r"(af[mi][2]), "r"(af[mi][3]),       \
                      "r"(bf[ni][0]), "r"(bf[ni][1]));                                      \
            }                                                                               \
    }                                                                                       \
    }

template<int EPI>
__global__ __launch_bounds__(256, 2) void hgemm(
    const __half* __restrict__ A, int lda, size_t sA,
    const unsigned int* __restrict__ Bw, size_t sB,
    const float* __restrict__ bias,
    float* __restrict__ C, size_t sC,
    __half* __restrict__ Ch, size_t sCh,
    const float* __restrict__ Add, size_t sAdd,
    int M, int K, int N)
{
    const int bz = blockIdx.z;
    A += (size_t)bz * sA;
    Bw += (size_t)bz * sB;

    extern __shared__ __align__(16) char dsmem[];
    __half* Asm = (__half*)dsmem;
    unsigned int* Bsm = (unsigned int*)(dsmem + 3 * A_STG * 2);

    const int tid = threadIdx.x, lane = tid & 31, warp = tid >> 5;
    const int gid = lane >> 2, tig = lane & 3;
    const int wm = (warp >> 2) * 64, wn = (warp & 3) * 32;
    const int bm = blockIdx.y * 128, bn = blockIdx.x * 128;

    const int arow = tid >> 1, ac = (tid & 1) * 16;
    const __half* Ap = A + (size_t)(bm + arow) * lda + ac;
    const int apred = ((bm + arow) < M) ? 16 : 0;
    const int brow = tid >> 4, bcw = (tid & 15) * 8;
    const unsigned int* Bp = Bw + (size_t)brow * N + bn + bcw;

    float acc[4][4][4];
    #pragma unroll
    for (int mi = 0; mi < 4; mi++)
        #pragma unroll
        for (int ni = 0; ni < 4; ni++)
            #pragma unroll
            for (int q = 0; q < 4; q++) acc[mi][ni][q] = 0.f;

    const int nk = K >> 5;

    auto stage = [&](int kb, int buf) {
        unsigned int sa = (unsigned int)__cvta_generic_to_shared(Asm + (size_t)buf * A_STG + arow * AHSTR + ac);
        const __half* ga = Ap + kb * 32;
        asm volatile("cp.async.ca.shared.global [%0], [%1], 16, %2;\n" :: "r"(sa), "l"(ga), "r"(apred));
        asm volatile("cp.async.ca.shared.global [%0], [%1], 16, %2;\n" :: "r"(sa + 16), "l"(ga + 8), "r"(apred));
        unsigned int sb = (unsigned int)__cvta_generic_to_shared(Bsm + (size_t)buf * B_STG + brow * BWSTR + bcw);
        const unsigned int* gb = Bp + (size_t)kb * 16 * N;
        asm volatile("cp.async.cg.shared.global [%0], [%1], 16;\n" :: "r"(sb), "l"(gb));
        asm volatile("cp.async.cg.shared.global [%0], [%1], 16;\n" :: "r"(sb + 16), "l"(gb + 4));
        asm volatile("cp.async.commit_group;\n");
    };

    stage(0, 0);
    if (nk > 1) stage(1, 1);
    for (int kb = 0; kb < nk; kb++) {
        const int cur = kb % 3;
        if (kb + 1 < nk) { asm volatile("cp.async.wait_group 1;\n"); }
        else             { asm volatile("cp.async.wait_group 0;\n"); }
        __syncthreads();
        if (kb + 2 < nk) stage(kb + 2, (kb + 2) % 3);
        HGEMM_CORE();
    }

    #pragma unroll
    for (int mi = 0; mi < 4; mi++) {
        const int r0 = bm + wm + mi * 16 + gid;
        const int r1 = r0 + 8;
        const bool ok0 = r0 < M, ok1 = r1 < M;
        const float bv0 = (bias && ok0) ? bias[r0] : 0.f;
        const float bv1 = (bias && ok1) ? bias[r1] : 0.f;
        #pragma unroll
        for (int ni = 0; ni < 4; ni++) {
            const int cc = bn + wn + ni * 8 + 2 * tig;
            #pragma unroll
            for (int half_m = 0; half_m < 2; half_m++) {
                const int r = half_m ? r1 : r0;
                if (!(half_m ? ok1 : ok0)) continue;
                float v0 = acc[mi][ni][half_m * 2 + 0] + (half_m ? bv1 : bv0);
                float v1 = acc[mi][ni][half_m * 2 + 1] + (half_m ? bv1 : bv0);
                if (EPI == 2) {
                    size_t o = (size_t)bz * sC + (size_t)r * N + cc;
                    const float2 ad = *(const float2*)&Add[(size_t)bz * sAdd + (size_t)r * N + cc];
                    C[o] = fmaxf(v0, 0.f) + ad.x;
                    C[o + 1] = fmaxf(v1, 0.f) + ad.y;
                } else if (EPI == 3) {
                    size_t o = (size_t)bz * sC + (size_t)r * N + cc;
                    *(float2*)&C[o] = make_float2(v0, v1);
                    size_t oh = (size_t)bz * sCh + ((size_t)(r >> 1) * N + cc) * 2 + (r & 1);
                    Ch[oh] = __float2half(v0);
                    Ch[oh + 2] = __float2half(v1);
                } else if (EPI == 6) {
                    const int w = cc & 127;
                    const __half h0 = __float2half(v0), h1 = __float2half(v1);
                    const size_t rowoff = (size_t)r * HWSZ + (size_t)(cc & ~127);
                    __half* c0 = g_offh3 + ((size_t)0 * BATCH + bz) * CC * HWSZ + rowoff;
                    __half* c1 = g_offh3 + ((size_t)1 * BATCH + bz) * CC * HWSZ + rowoff;
                    __half* c2 = g_offh3 + ((size_t)2 * BATCH + bz) * CC * HWSZ + rowoff;
                    *(__half2*)&c1[w] = __halves2half2(h0, h1);
                    c0[w + 1] = h0;
                    if (w + 2 < 128) c0[w + 2] = h1;
                    if (w > 0) c2[w - 1] = h0;
                    c2[w] = h1;
                }
            }
        }
    }
}

// ---------------- fused im2col + fp16 GEMM for the 3x3 offset/mask conv ----------------
__global__ __launch_bounds__(256, 2) void hgemm_om(
    const float* __restrict__ bias, float* __restrict__ C)
{
    const int bz = blockIdx.z;
    const __half* A = g_omwh;
    float* Cb = C + (size_t)bz * OMCH * HWSZ;

    extern __shared__ __align__(16) char dsmem[];
    __half* Asm = (__half*)dsmem;
    unsigned int* Bsm = (unsigned int*)(dsmem + 3 * A_STG * 2);

    const int tid = threadIdx.x, lane = tid & 31, warp = tid >> 5;
    const int gid = lane >> 2, tig = lane & 3;
    const int wm = (warp >> 2) * 64, wn = (warp & 3) * 32;
    const int bm = blockIdx.y * 128;
    const int h = blockIdx.x;
    const int bn = h * 128;

    const int arow = tid >> 1, ac = (tid & 1) * 16;
    const __half* Ap = A + (size_t)(bm + arow) * KBIG + ac;
    const int apred = ((bm + arow) < OMCH) ? 16 : 0;

    const int kp = tid >> 4;
    const int chunk = tid & 15;

    float acc[4][4][4];
    #pragma unroll
    for (int mi = 0; mi < 4; mi++)
        #pragma unroll
        for (int ni = 0; ni < 4; ni++)
            #pragma unroll
            for (int q = 0; q < 4; q++) acc[mi][ni][q] = 0.f;

    const int nk = KBIG / 32;   // 36
    uint4 bva, bvb;

    auto load_a = [&](int kb, int buf) {
        unsigned int sa = (unsigned int)__cvta_generic_to_shared(Asm + (size_t)buf * A_STG + arow * AHSTR + ac);
        const __half* ga = Ap + kb * 32;
        asm volatile("cp.async.ca.shared.global [%0], [%1], 16, %2;\n" :: "r"(sa), "l"(ga), "r"(apred));
        asm volatile("cp.async.ca.shared.global [%0], [%1], 16, %2;\n" :: "r"(sa + 16), "l"(ga + 8), "r"(apred));
        asm volatile("cp.async.commit_group;\n");
    };
    auto load_b_regs = [&](int kb) {
        #pragma unroll
        for (int rr = 0; rr < 2; rr++) {
            int ck = kb * 32 + 2 * kp + rr;
            int c  = ck / 9;
            int kk = ck - 9 * c;
            int dy = kk / 3 - 1;
            int ci = kk - (kk / 3) * 3;     // dx + 1
            int hs = h + dy;
            uint4 v = make_uint4(0u, 0u, 0u, 0u);
            if ((unsigned)hs < 128u) {
                const __half* src = g_offh3 + (((size_t)ci * BATCH + bz) * CC + c) * HWSZ
                                  + hs * 128 + chunk * 8;
                v = *(const uint4*)src;
            }
            if (rr == 0) bva = v; else bvb = v;
        }
    };
    auto sts_b = [&](int buf) {
        unsigned int* dst = Bsm + (size_t)buf * B_STG + kp * BWSTR + chunk * 8;
        uint4 o1, o2;
        o1.x = __byte_perm(bva.x, bvb.x, 0x5410);
        o1.y = __byte_perm(bva.x, bvb.x, 0x7632);
        o1.z = __byte_perm(bva.y, bvb.y, 0x5410);
        o1.w = __byte_perm(bva.y, bvb.y, 0x7632);
        o2.x = __byte_perm(bva.z, bvb.z, 0x5410);
        o2.y = __byte_perm(bva.z, bvb.z, 0x7632);
        o2.z = __byte_perm(bva.w, bvb.w, 0x5410);
        o2.w = __byte_perm(bva.w, bvb.w, 0x7632);
        *(uint4*)dst = o1;
        *(uint4*)(dst + 4) = o2;
    };

    load_a(0, 0);
    load_b_regs(0);
    asm volatile("cp.async.wait_group 0;\n");
    sts_b(0);
    __syncthreads();

    for (int kb = 0; kb < nk; kb++) {
        const int cur = kb % 3;
        if (kb + 1 < nk) {
            load_a(kb + 1, (kb + 1) % 3);
            load_b_regs(kb + 1);
        }
        HGEMM_CORE();
        if (kb + 1 < nk) {
            asm volatile("cp.async.wait_group 0;\n");
            sts_b((kb + 1) % 3);
        }
        __syncthreads();
    }

    #pragma unroll
    for (int mi = 0; mi < 4; mi++) {
        const int r0 = bm + wm + mi * 16 + gid;
        const int r1 = r0 + 8;
        const bool ok0 = r0 < OMCH, ok1 = r1 < OMCH;
        const float bv0 = ok0 ? bias[r0] : 0.f;
        const float bv1 = ok1 ? bias[r1] : 0.f;
        #pragma unroll
        for (int ni = 0; ni < 4; ni++) {
            const int cc = bn + wn + ni * 8 + 2 * tig;
            if (ok0) {
                size_t o = (size_t)r0 * HWSZ + cc;
                *(float2*)&Cb[o] = make_float2(acc[mi][ni][0] + bv0, acc[mi][ni][1] + bv0);
            }
            if (ok1) {
                size_t o = (size_t)r1 * HWSZ + cc;
                *(float2*)&Cb[o] = make_float2(acc[mi][ni][2] + bv1, acc[mi][ni][3] + bv1);
            }
        }
    }
}

// ---------------- launch ----------------
extern "C" void kernel_launch(void* const* d_in, const int* in_sizes, int n_in,
                              void* d_out, int out_size) {
    const float* feat_l  = (const float*)d_in[0];
    const float* feat_s  = (const float*)d_in[1];
    const float* atten_w = (const float*)d_in[2];
    const float* atten_b = (const float*)d_in[3];
    const float* bn_g    = (const float*)d_in[4];
    const float* bn_b    = (const float*)d_in[5];
    const float* bn_m    = (const float*)d_in[6];
    const float* bn_v    = (const float*)d_in[7];
    const float* fsm_w   = (const float*)d_in[8];
    const float* fsm_b   = (const float*)d_in[9];
    const float* om_b    = (const float*)d_in[12];
    const float* dcn_b   = (const float*)d_in[14];
    float* out = (float*)d_out;

    float *p_cat, *p_om;
    __half *p_armWh, *p_offwh, *p_dcnwh, *p_flh, *p_cath, *p_Sh;
    cudaGetSymbolAddress((void**)&p_cat,   g_cat);
    cudaGetSymbolAddress((void**)&p_om,    g_om);
    cudaGetSymbolAddress((void**)&p_armWh, g_armWh);
    cudaGetSymbolAddress((void**)&p_offwh, g_offwh);
    cudaGetSymbolAddress((void**)&p_dcnwh, g_dcnwh);
    cudaGetSymbolAddress((void**)&p_flh,   g_flh);
    cudaGetSymbolAddress((void**)&p_cath,  g_cath);
    cudaGetSymbolAddress((void**)&p_Sh,    g_Sh);

    cudaFuncSetAttribute(hgemm<2>, cudaFuncAttributeMaxDynamicSharedMemorySize, SMEM_BYTES);
    cudaFuncSetAttribute(hgemm<3>, cudaFuncAttributeMaxDynamicSharedMemorySize, SMEM_BYTES);
    cudaFuncSetAttribute(hgemm<6>, cudaFuncAttributeMaxDynamicSharedMemorySize, SMEM_BYTES);
    cudaFuncSetAttribute(hgemm_om, cudaFuncAttributeMaxDynamicSharedMemorySize, SMEM_BYTES);

    // 1) SE gate + weight packing (+ offh3 edge zeroing) + prep
    pool_kernel<<<BATCH * CC, 256>>>(feat_l);
    atten_kernel<<<1, 256>>>(atten_w, atten_b, bn_g, bn_b, bn_m, bn_v);
    armw_kernel<<<128, 256>>>(fsm_w);
    whpack_kernel<<<(OMCH * KBIG + 255) / 256, 256>>>(
        (const float*)d_in[11], (const float*)d_in[13], (const float*)d_in[10]);
    prep_kernel<<<(BATCH * CC * HWSZ + 255) / 256, 256>>>(feat_l, feat_s);

    // 2) feat_arm = armW @ feat_l + fsm_b -> fp32 g_cat + fp16 g_cath
    hgemm<3><<<dim3(HWSZ / 128, 1, BATCH), 256, SMEM_BYTES>>>(
        p_armWh, CC, (size_t)CC * CC,
        (const unsigned int*)p_flh, (size_t)(CC / 2) * HWSZ,
        fsm_b,
        p_cat, (size_t)2 * CC * HWSZ,
        p_cath, (size_t)2 * CC * HWSZ,
        nullptr, 0,
        CC, CC, HWSZ);

    // 3) off_feat = off_w @ [feat_arm; feat_up] -> 3 shifted fp16 copies g_offh3
    hgemm<6><<<dim3(HWSZ / 128, 1, BATCH), 256, SMEM_BYTES>>>(
        p_offwh, 2 * CC, 0,
        (const unsigned int*)p_cath, (size_t)CC * HWSZ,
        nullptr,
        nullptr, 0,
        nullptr, 0,
        nullptr, 0,
        CC, 2 * CC, HWSZ);

    // 4) fused im2col + 3x3 conv (M=216, K=1152) -> fp32 g_om
    hgemm_om<<<dim3(128, 2, BATCH), 256, SMEM_BYTES>>>(om_b, p_om);

    // 5) bilinear sample + mask -> fp16 interleaved g_Sh
    sample_kernel<<<(BATCH * DGRP * KPTS * HWSZ + 255) / 256, 256>>>();

    // 6) DCN GEMM + relu + bias + feat_arm -> out
    hgemm<2><<<dim3(HWSZ / 128, 1, BATCH), 256, SMEM_BYTES>>>(
        p_dcnwh, KBIG, 0,
        (const unsigned int*)p_Sh, (size_t)(KBIG / 2) * HWSZ,
        dcn_b,
        out, (size_t)CC * HWSZ,
        nullptr, 0,
        p_cat, (size_t)2 * CC * HWSZ,
        CC, KBIG, HWSZ);
}

// round 10
// speedup vs baseline: 1.0541x; 1.0541x over previous
#include <cuda_runtime.h>
#include <cuda_fp16.h>
#include <cstdint>
#include <stdint.h>
#include <math.h>

// ---------------- problem constants ----------------
#define BATCH 2
#define CC    128
#define HWSZ  16384         // 128*128
#define HS    64
#define DGRP  8
#define CG    16
#define KPTS  9
#define OMCH  216           // DG*3*KK
#define KBIG  1152          // CC*9

// ---------------- scratch ----------------
__device__ float g_pooled[BATCH * CC];
__device__ float g_scale [BATCH * CC];
__device__ float g_cat   [(size_t)BATCH * 2 * CC * HWSZ];     // fp32: rows 0..127 feat_arm, 128..255 feat_up
__device__ float g_om    [(size_t)BATCH * OMCH * HWSZ];       // fp32 offsets/mask

__device__ __align__(16) __half g_armWh[BATCH * CC * CC];     // fp16 A matrices
__device__ __align__(16) __half g_offwh[CC * 2 * CC];
__device__ __align__(16) __half g_omwh [OMCH * KBIG];
__device__ __align__(16) __half g_dcnwh[CC * KBIG];

// fp16 B operands, k-pair-interleaved word layout: word[kp][n] = (half(2kp,n), half(2kp+1,n))
__device__ __align__(16) __half g_flh  [(size_t)BATCH * CC * HWSZ];       // feat_l
__device__ __align__(16) __half g_cath [(size_t)BATCH * 2 * CC * HWSZ];   // [feat_arm; feat_up]
__device__ __align__(16) __half g_Sh   [(size_t)BATCH * KBIG * HWSZ];     // sampled DCN input
// THREE pre-shifted fp16 copies of off_feat: copy ci (dx=ci-1): copy[ci][b][c][h][x] = off[b][c][h][x+dx]
__device__ __align__(16) __half g_offh3[(size_t)3 * BATCH * CC * HWSZ];

// ---------------- small kernels ----------------
__global__ void pool_kernel(const float* __restrict__ x) {
    int bc = blockIdx.x;
    const float4* p = (const float4*)(x + (size_t)bc * HWSZ);
    float s = 0.f;
    for (int i = threadIdx.x; i < HWSZ / 4; i += 256) {
        float4 v = p[i];
        s += v.x + v.y + v.z + v.w;
    }
    __shared__ float sh[256];
    sh[threadIdx.x] = s;
    __syncthreads();
    for (int o = 128; o > 0; o >>= 1) {
        if (threadIdx.x < o) sh[threadIdx.x] += sh[threadIdx.x + o];
        __syncthreads();
    }
    if (threadIdx.x == 0) g_pooled[bc] = sh[0] * (1.0f / HWSZ);
}

__global__ void atten_kernel(const float* __restrict__ aw, const float* __restrict__ ab,
                             const float* __restrict__ bg, const float* __restrict__ bb,
                             const float* __restrict__ bm, const float* __restrict__ bv) {
    int t = threadIdx.x;
    int b = t >> 7, o = t & 127;
    float a = ab[o];
    const float* pr = g_pooled + b * CC;
    const float* wr = aw + o * CC;
    #pragma unroll 4
    for (int c = 0; c < CC; c++) a += pr[c] * wr[c];
    a = (a - bm[o]) * rsqrtf(bv[o] + 1e-5f) * bg[o] + bb[o];
    g_scale[t] = 1.f + 1.f / (1.f + expf(-a));
}

__global__ void armw_kernel(const float* __restrict__ fsm_w) {
    int i = blockIdx.x * blockDim.x + threadIdx.x;
    int c = i & 127;
    int bo = i >> 7;
    int o = bo & 127;
    int b = bo >> 7;
    g_armWh[i] = __float2half(fsm_w[o * CC + c] * g_scale[b * CC + c]);
}

// weight packing + zero the never-written edge columns of g_offh3
__global__ void whpack_kernel(const float* __restrict__ om_w,
                              const float* __restrict__ dcn_w,
                              const float* __restrict__ off_w) {
    int i = blockIdx.x * blockDim.x + threadIdx.x;
    if (i < OMCH * KBIG) g_omwh[i] = __float2half(om_w[i]);
    if (i < CC * KBIG)   g_dcnwh[i] = __float2half(dcn_w[i]);
    if (i < CC * 2 * CC) g_offwh[i] = __float2half(off_w[i]);
    if (i < 2 * BATCH * CC * 128) {
        int e = i & 1;
        int t = i >> 1;
        int h = t & 127; t >>= 7;
        int c = t & 127; t >>= 7;
        int b = t & 1;
        int ci = e ? 2 : 0;
        int x  = e ? 127 : 0;
        g_offh3[(((size_t)ci * BATCH + b) * CC + c) * HWSZ + h * 128 + x] = __float2half(0.f);
    }
}

// fused: feat_l fp32->fp16 interleaved  AND  upsample feat_s (fp32 + fp16 interleaved)
__global__ void prep_kernel(const float* __restrict__ fl, const float* __restrict__ fs) {
    int i = blockIdx.x * blockDim.x + threadIdx.x;
    if (i >= BATCH * CC * HWSZ) return;
    int n = i & (HWSZ - 1);
    int bc = i >> 14;
    int b = bc >> 7, c = bc & 127;
    g_flh[((size_t)b * (CC / 2) + (c >> 1)) * (2 * HWSZ) + n * 2 + (c & 1)] = __float2half(fl[i]);
    int h = n >> 7, w = n & 127;
    float fy = (h * 63.0f) / 127.0f;
    float fx = (w * 63.0f) / 127.0f;
    int y0 = (int)floorf(fy); float wy = fy - y0; int y1 = min(y0 + 1, 63);
    int x0 = (int)floorf(fx); float wx = fx - x0; int x1 = min(x0 + 1, 63);
    const float* p = fs + (size_t)bc * (HS * HS);
    float v = p[y0 * HS + x0] * (1.f - wy) * (1.f - wx)
            + p[y0 * HS + x1] * (1.f - wy) * wx
            + p[y1 * HS + x0] * wy * (1.f - wx)
            + p[y1 * HS + x1] * wy * wx;
    g_cat[((size_t)b * 2 * CC + CC + c) * HWSZ + n] = v;
    g_cath[((size_t)b * CC + (CC >> 1) + (c >> 1)) * (2 * HWSZ) + n * 2 + (c & 1)] = __float2half(v);
}

// bilinear sample + mask -> fp16 interleaved g_Sh ; corners read as fp16 channel-pair words
__global__ void sample_kernel() {
    int i = blockIdx.x * blockDim.x + threadIdx.x;
    if (i >= BATCH * DGRP * KPTS * HWSZ) return;
    int n = i & (HWSZ - 1);
    int t = i >> 14;
    int k = t % KPTS; t /= KPTS;
    int g = t & 7;
    int b = t >> 3;
    int h = n >> 7, w = n & 127;

    const float* om = g_om + (size_t)b * OMCH * HWSZ;
    int gk = g * KPTS + k;
    float offy = om[(size_t)gk * HWSZ + n];
    float offx = om[(size_t)(72 + gk) * HWSZ + n];
    float mm   = om[(size_t)(144 + gk) * HWSZ + n];
    mm = 1.f / (1.f + expf(-mm));

    float py = (float)(h + k / 3 - 1) + offy;
    float px = (float)(w + k % 3 - 1) + offx;
    float y0f = floorf(py), x0f = floorf(px);
    float ly = py - y0f, lx = px - x0f;
    int y0 = (int)y0f, x0 = (int)x0f;
    int y1 = y0 + 1, x1 = x0 + 1;
    bool vy0 = (y0 >= 0 && y0 < 128), vy1 = (y1 >= 0 && y1 < 128);
    bool vx0 = (x0 >= 0 && x0 < 128), vx1 = (x1 >= 0 && x1 < 128);
    int cy0 = min(max(y0, 0), 127), cy1 = min(max(y1, 0), 127);
    int cx0 = min(max(x0, 0), 127), cx1 = min(max(x1, 0), 127);
    float w00 = (vy0 && vx0) ? (1.f - ly) * (1.f - lx) * mm : 0.f;
    float w01 = (vy0 && vx1) ? (1.f - ly) * lx * mm : 0.f;
    float w10 = (vy1 && vx0) ? ly * (1.f - lx) * mm : 0.f;
    float w11 = (vy1 && vx1) ? ly * lx * mm : 0.f;
    int i00 = (cy0 << 7) + cx0, i01 = (cy0 << 7) + cx1;
    int i10 = (cy1 << 7) + cx0, i11 = (cy1 << 7) + cx1;

    const unsigned int* cw = (const unsigned int*)g_cath + (size_t)b * CC * HWSZ;
    #pragma unroll
    for (int cp = 0; cp < 8; cp++) {
        const unsigned int* rowp = cw + (size_t)(64 + g * 8 + cp) * HWSZ;
        float2 c00 = __half22float2(*(const __half2*)&rowp[i00]);
        float2 c01 = __half22float2(*(const __half2*)&rowp[i01]);
        float2 c10 = __half22float2(*(const __half2*)&rowp[i10]);
        float2 c11 = __half22float2(*(const __half2*)&rowp[i11]);
        float ve = w00 * c00.x + w01 * c01.x + w10 * c10.x + w11 * c11.x;
        float vo = w00 * c00.y + w01 * c01.y + w10 * c10.y + w11 * c11.y;
        int re = g * 144 + (2 * cp) * 9 + k;
        int ro = re + 9;
        g_Sh[((size_t)b * (KBIG / 2) + (re >> 1)) * (2 * HWSZ) + n * 2 + (re & 1)] = __float2half(ve);
        g_Sh[((size_t)b * (KBIG / 2) + (ro >> 1)) * (2 * HWSZ) + n * 2 + (ro & 1)] = __float2half(vo);
    }
}

// ---------------- FP16 tensor-core GEMM ----------------
// BM=BN=128, BK=32 halves, 256 threads, 8 warps 2x4, m16n8k16,
// 3-stage cp.async pipeline, one __syncthreads per k-iter, ldmatrix.x4 A frags.
#define AHSTR 40   // halves per A smem row (80B); 8-row groups hit distinct banks
#define BWSTR 136  // words per B kp-row
#define A_STG (128 * AHSTR)          // halves per A stage
#define B_STG (16 * BWSTR)           // words per B stage
#define SMEM_BYTES (3 * (A_STG * 2 + B_STG * 4))   // 56832

// A fragment via ldmatrix.x4: lane (l&15) -> row, (l>>4)*8 -> k-offset.
// matrix0 = rows g..g+7 @k0, 1 = rows +8, 2 = @k0+8, 3 = both -> exactly {a0,a1,a2,a3}.
#define HGEMM_CORE()                                                                        \
    {                                                                                       \
    const unsigned int abase = (unsigned int)__cvta_generic_to_shared(                      \
        Asm + (size_t)cur * A_STG);                                                         \
    const unsigned int* bw = Bsm + (size_t)cur * B_STG;                                     \
    const int l15 = lane & 15, lhi8 = (lane >> 4) * 8;                                      \
    _Pragma("unroll")                                                                       \
    for (int ks = 0; ks < 2; ks++) {                                                        \
        unsigned int af[4][4], bf[4][2];                                                    \
        _Pragma("unroll")                                                                   \
        for (int mi = 0; mi < 4; mi++) {                                                    \
            unsigned int aaddr = abase +                                                    \
                ((unsigned int)((wm + mi * 16 + l15) * AHSTR + ks * 16 + lhi8) << 1);       \
            asm volatile(                                                                   \
                "ldmatrix.sync.aligned.m8n8.x4.shared.b16 {%0,%1,%2,%3}, [%4];\n"           \
                : "=r"(af[mi][0]), "=r"(af[mi][1]), "=r"(af[mi][2]), "=r"(af[mi][3])        \
                : "r"(aaddr));                                                              \
        }                                                                                   \
        _Pragma("unroll")                                                                   \
        for (int ni = 0; ni < 4; ni++) {                                                    \
            int col = wn + ni * 8 + gid;                                                    \
            bf[ni][0] = bw[(ks * 8 + tig) * BWSTR + col];                                   \
            bf[ni][1] = bw[(ks * 8 + tig + 4) * BWSTR + col];                               \
        }                                                                                   \
        _Pragma("unroll")                                                                   \
        for (int mi = 0; mi < 4; mi++)                                                      \
            _Pragma("unroll")                                                               \
            for (int ni = 0; ni < 4; ni++) {                                                \
                asm volatile(                                                               \
                    "mma.sync.aligned.m16n8k16.row.col.f32.f16.f16.f32 "                    \
                    "{%0,%1,%2,%3}, {%4,%5,%6,%7}, {%8,%9}, {%0,%1,%2,%3};\n"               \
                    : "+f"(acc[mi][ni][0]), "+f"(acc[mi][ni][1]),                           \
                      "+f"(acc[mi][ni][2]), "+f"(acc[mi][ni][3])                            \
                    : "r"(af[mi][0]), "r"(af[mi][1]), "r"(af[mi][2]), "r"(af[mi][3]),       \
                      "r"(bf[ni][0]), "r"(bf[ni][1]));                                      \
            }                                                                               \
    }                                                                                       \
    }

template<int EPI>
__global__ __launch_bounds__(256, 2) void hgemm(
    const __half* __restrict__ A, int lda, size_t sA,
    const unsigned int* __restrict__ Bw, size_t sB,
    const float* __restrict__ bias,
    float* __restrict__ C, size_t sC,
    __half* __restrict__ Ch, size_t sCh,
    const float* __restrict__ Add, size_t sAdd,
    int M, int K, int N)
{
    const int bz = blockIdx.z;
    A += (size_t)bz * sA;
    Bw += (size_t)bz * sB;

    extern __shared__ __align__(16) char dsmem[];
    __half* Asm = (__half*)dsmem;
    unsigned int* Bsm = (unsigned int*)(dsmem + 3 * A_STG * 2);

    const int tid = threadIdx.x, lane = tid & 31, warp = tid >> 5;
    const int gid = lane >> 2, tig = lane & 3;
    const int wm = (warp >> 2) * 64, wn = (warp & 3) * 32;
    const int bm = blockIdx.y * 128, bn = blockIdx.x * 128;

    const int arow = tid >> 1, ac = (tid & 1) * 16;
    const __half* Ap = A + (size_t)(bm + arow) * lda + ac;
    const int apred = ((bm + arow) < M) ? 16 : 0;
    const int brow = tid >> 4, bcw = (tid & 15) * 8;
    const unsigned int* Bp = Bw + (size_t)brow * N + bn + bcw;

    float acc[4][4][4];
    #pragma unroll
    for (int mi = 0; mi < 4; mi++)
        #pragma unroll
        for (int ni = 0; ni < 4; ni++)
            #pragma unroll
            for (int q = 0; q < 4; q++) acc[mi][ni][q] = 0.f;

    const int nk = K >> 5;

    auto stage = [&](int kb, int buf) {
        unsigned int sa = (unsigned int)__cvta_generic_to_shared(Asm + (size_t)buf * A_STG + arow * AHSTR + ac);
        const __half* ga = Ap + kb * 32;
        asm volatile("cp.async.ca.shared.global [%0], [%1], 16, %2;\n" :: "r"(sa), "l"(ga), "r"(apred));
        asm volatile("cp.async.ca.shared.global [%0], [%1], 16, %2;\n" :: "r"(sa + 16), "l"(ga + 8), "r"(apred));
        unsigned int sb = (unsigned int)__cvta_generic_to_shared(Bsm + (size_t)buf * B_STG + brow * BWSTR + bcw);
        const unsigned int* gb = Bp + (size_t)kb * 16 * N;
        asm volatile("cp.async.cg.shared.global [%0], [%1], 16;\n" :: "r"(sb), "l"(gb));
        asm volatile("cp.async.cg.shared.global [%0], [%1], 16;\n" :: "r"(sb + 16), "l"(gb + 4));
        asm volatile("cp.async.commit_group;\n");
    };

    stage(0, 0);
    if (nk > 1) stage(1, 1);
    for (int kb = 0; kb < nk; kb++) {
        const int cur = kb % 3;
        if (kb + 1 < nk) { asm volatile("cp.async.wait_group 1;\n"); }
        else             { asm volatile("cp.async.wait_group 0;\n"); }
        __syncthreads();
        if (kb + 2 < nk) stage(kb + 2, (kb + 2) % 3);
        HGEMM_CORE();
    }

    #pragma unroll
    for (int mi = 0; mi < 4; mi++) {
        const int r0 = bm + wm + mi * 16 + gid;
        const int r1 = r0 + 8;
        const bool ok0 = r0 < M, ok1 = r1 < M;
        const float bv0 = (bias && ok0) ? bias[r0] : 0.f;
        const float bv1 = (bias && ok1) ? bias[r1] : 0.f;
        #pragma unroll
        for (int ni = 0; ni < 4; ni++) {
            const int cc = bn + wn + ni * 8 + 2 * tig;
            #pragma unroll
            for (int half_m = 0; half_m < 2; half_m++) {
                const int r = half_m ? r1 : r0;
                if (!(half_m ? ok1 : ok0)) continue;
                float v0 = acc[mi][ni][half_m * 2 + 0] + (half_m ? bv1 : bv0);
                float v1 = acc[mi][ni][half_m * 2 + 1] + (half_m ? bv1 : bv0);
                if (EPI == 2) {
                    size_t o = (size_t)bz * sC + (size_t)r * N + cc;
                    const float2 ad = *(const float2*)&Add[(size_t)bz * sAdd + (size_t)r * N + cc];
                    C[o] = fmaxf(v0, 0.f) + ad.x;
                    C[o + 1] = fmaxf(v1, 0.f) + ad.y;
                } else if (EPI == 3) {
                    size_t o = (size_t)bz * sC + (size_t)r * N + cc;
                    *(float2*)&C[o] = make_float2(v0, v1);
                    size_t oh = (size_t)bz * sCh + ((size_t)(r >> 1) * N + cc) * 2 + (r & 1);
                    Ch[oh] = __float2half(v0);
                    Ch[oh + 2] = __float2half(v1);
                } else if (EPI == 6) {
                    const int w = cc & 127;
                    const __half h0 = __float2half(v0), h1 = __float2half(v1);
                    const size_t rowoff = (size_t)r * HWSZ + (size_t)(cc & ~127);
                    __half* c0 = g_offh3 + ((size_t)0 * BATCH + bz) * CC * HWSZ + rowoff;
                    __half* c1 = g_offh3 + ((size_t)1 * BATCH + bz) * CC * HWSZ + rowoff;
                    __half* c2 = g_offh3 + ((size_t)2 * BATCH + bz) * CC * HWSZ + rowoff;
                    *(__half2*)&c1[w] = __halves2half2(h0, h1);
                    c0[w + 1] = h0;
                    if (w + 2 < 128) c0[w + 2] = h1;
                    if (w > 0) c2[w - 1] = h0;
                    c2[w] = h1;
                }
            }
        }
    }
}

// ---------------- fused im2col + fp16 GEMM for the 3x3 offset/mask conv ----------------
__global__ __launch_bounds__(256, 2) void hgemm_om(
    const float* __restrict__ bias, float* __restrict__ C)
{
    const int bz = blockIdx.z;
    const __half* A = g_omwh;
    float* Cb = C + (size_t)bz * OMCH * HWSZ;

    extern __shared__ __align__(16) char dsmem[];
    __half* Asm = (__half*)dsmem;
    unsigned int* Bsm = (unsigned int*)(dsmem + 3 * A_STG * 2);

    const int tid = threadIdx.x, lane = tid & 31, warp = tid >> 5;
    const int gid = lane >> 2, tig = lane & 3;
    const int wm = (warp >> 2) * 64, wn = (warp & 3) * 32;
    const int bm = blockIdx.y * 128;
    const int h = blockIdx.x;
    const int bn = h * 128;

    const int arow = tid >> 1, ac = (tid & 1) * 16;
    const __half* Ap = A + (size_t)(bm + arow) * KBIG + ac;
    const int apred = ((bm + arow) < OMCH) ? 16 : 0;

    const int kp = tid >> 4;
    const int chunk = tid & 15;

    float acc[4][4][4];
    #pragma unroll
    for (int mi = 0; mi < 4; mi++)
        #pragma unroll
        for (int ni = 0; ni < 4; ni++)
            #pragma unroll
            for (int q = 0; q < 4; q++) acc[mi][ni][q] = 0.f;

    const int nk = KBIG / 32;   // 36
    uint4 bva, bvb;

    auto load_a = [&](int kb, int buf) {
        unsigned int sa = (unsigned int)__cvta_generic_to_shared(Asm + (size_t)buf * A_STG + arow * AHSTR + ac);
        const __half* ga = Ap + kb * 32;
        asm volatile("cp.async.ca.shared.global [%0], [%1], 16, %2;\n" :: "r"(sa), "l"(ga), "r"(apred));
        asm volatile("cp.async.ca.shared.global [%0], [%1], 16, %2;\n" :: "r"(sa + 16), "l"(ga + 8), "r"(apred));
        asm volatile("cp.async.commit_group;\n");
    };
    auto load_b_regs = [&](int kb) {
        #pragma unroll
        for (int rr = 0; rr < 2; rr++) {
            int ck = kb * 32 + 2 * kp + rr;
            int c  = ck / 9;
            int kk = ck - 9 * c;
            int dy = kk / 3 - 1;
            int ci = kk - (kk / 3) * 3;     // dx + 1
            int hs = h + dy;
            uint4 v = make_uint4(0u, 0u, 0u, 0u);
            if ((unsigned)hs < 128u) {
                const __half* src = g_offh3 + (((size_t)ci * BATCH + bz) * CC + c) * HWSZ
                                  + hs * 128 + chunk * 8;
                v = *(const uint4*)src;
            }
            if (rr == 0) bva = v; else bvb = v;
        }
    };
    auto sts_b = [&](int buf) {
        unsigned int* dst = Bsm + (size_t)buf * B_STG + kp * BWSTR + chunk * 8;
        uint4 o1, o2;
        o1.x = __byte_perm(bva.x, bvb.x, 0x5410);
        o1.y = __byte_perm(bva.x, bvb.x, 0x7632);
        o1.z = __byte_perm(bva.y, bvb.y, 0x5410);
        o1.w = __byte_perm(bva.y, bvb.y, 0x7632);
        o2.x = __byte_perm(bva.z, bvb.z, 0x5410);
        o2.y = __byte_perm(bva.z, bvb.z, 0x7632);
        o2.z = __byte_perm(bva.w, bvb.w, 0x5410);
        o2.w = __byte_perm(bva.w, bvb.w, 0x7632);
        *(uint4*)dst = o1;
        *(uint4*)(dst + 4) = o2;
    };

    load_a(0, 0);
    load_b_regs(0);
    asm volatile("cp.async.wait_group 0;\n");
    sts_b(0);
    __syncthreads();

    for (int kb = 0; kb < nk; kb++) {
        const int cur = kb % 3;
        if (kb + 1 < nk) {
            load_a(kb + 1, (kb + 1) % 3);
            load_b_regs(kb + 1);
        }
        HGEMM_CORE();
        if (kb + 1 < nk) {
            asm volatile("cp.async.wait_group 0;\n");
            sts_b((kb + 1) % 3);
        }
        __syncthreads();
    }

    #pragma unroll
    for (int mi = 0; mi < 4; mi++) {
        const int r0 = bm + wm + mi * 16 + gid;
        const int r1 = r0 + 8;
        const bool ok0 = r0 < OMCH, ok1 = r1 < OMCH;
        const float bv0 = ok0 ? bias[r0] : 0.f;
        const float bv1 = ok1 ? bias[r1] : 0.f;
        #pragma unroll
        for (int ni = 0; ni < 4; ni++) {
            const int cc = bn + wn + ni * 8 + 2 * tig;
            if (ok0) {
                size_t o = (size_t)r0 * HWSZ + cc;
                *(float2*)&Cb[o] = make_float2(acc[mi][ni][0] + bv0, acc[mi][ni][1] + bv0);
            }
            if (ok1) {
                size_t o = (size_t)r1 * HWSZ + cc;
                *(float2*)&Cb[o] = make_float2(acc[mi][ni][2] + bv1, acc[mi][ni][3] + bv1);
            }
        }
    }
}

// ---------------- launch ----------------
extern "C" void kernel_launch(void* const* d_in, const int* in_sizes, int n_in,
                              void* d_out, int out_size) {
    const float* feat_l  = (const float*)d_in[0];
    const float* feat_s  = (const float*)d_in[1];
    const float* atten_w = (const float*)d_in[2];
    const float* atten_b = (const float*)d_in[3];
    const float* bn_g    = (const float*)d_in[4];
    const float* bn_b    = (const float*)d_in[5];
    const float* bn_m    = (const float*)d_in[6];
    const float* bn_v    = (const float*)d_in[7];
    const float* fsm_w   = (const float*)d_in[8];
    const float* fsm_b   = (const float*)d_in[9];
    const float* om_b    = (const float*)d_in[12];
    const float* dcn_b   = (const float*)d_in[14];
    float* out = (float*)d_out;

    float *p_cat, *p_om;
    __half *p_armWh, *p_offwh, *p_dcnwh, *p_flh, *p_cath, *p_Sh;
    cudaGetSymbolAddress((void**)&p_cat,   g_cat);
    cudaGetSymbolAddress((void**)&p_om,    g_om);
    cudaGetSymbolAddress((void**)&p_armWh, g_armWh);
    cudaGetSymbolAddress((void**)&p_offwh, g_offwh);
    cudaGetSymbolAddress((void**)&p_dcnwh, g_dcnwh);
    cudaGetSymbolAddress((void**)&p_flh,   g_flh);
    cudaGetSymbolAddress((void**)&p_cath,  g_cath);
    cudaGetSymbolAddress((void**)&p_Sh,    g_Sh);

    cudaFuncSetAttribute(hgemm<2>, cudaFuncAttributeMaxDynamicSharedMemorySize, SMEM_BYTES);
    cudaFuncSetAttribute(hgemm<3>, cudaFuncAttributeMaxDynamicSharedMemorySize, SMEM_BYTES);
    cudaFuncSetAttribute(hgemm<6>, cudaFuncAttributeMaxDynamicSharedMemorySize, SMEM_BYTES);
    cudaFuncSetAttribute(hgemm_om, cudaFuncAttributeMaxDynamicSharedMemorySize, SMEM_BYTES);

    // 1) SE gate + weight packing (+ offh3 edge zeroing) + prep
    pool_kernel<<<BATCH * CC, 256>>>(feat_l);
    atten_kernel<<<1, 256>>>(atten_w, atten_b, bn_g, bn_b, bn_m, bn_v);
    armw_kernel<<<128, 256>>>(fsm_w);
    whpack_kernel<<<(OMCH * KBIG + 255) / 256, 256>>>(
        (const float*)d_in[11], (const float*)d_in[13], (const float*)d_in[10]);
    prep_kernel<<<(BATCH * CC * HWSZ + 255) / 256, 256>>>(feat_l, feat_s);

    // 2) feat_arm = armW @ feat_l + fsm_b -> fp32 g_cat + fp16 g_cath
    hgemm<3><<<dim3(HWSZ / 128, 1, BATCH), 256, SMEM_BYTES>>>(
        p_armWh, CC, (size_t)CC * CC,
        (const unsigned int*)p_flh, (size_t)(CC / 2) * HWSZ,
        fsm_b,
        p_cat, (size_t)2 * CC * HWSZ,
        p_cath, (size_t)2 * CC * HWSZ,
        nullptr, 0,
        CC, CC, HWSZ);

    // 3) off_feat = off_w @ [feat_arm; feat_up] -> 3 shifted fp16 copies g_offh3
    hgemm<6><<<dim3(HWSZ / 128, 1, BATCH), 256, SMEM_BYTES>>>(
        p_offwh, 2 * CC, 0,
        (const unsigned int*)p_cath, (size_t)CC * HWSZ,
        nullptr,
        nullptr, 0,
        nullptr, 0,
        nullptr, 0,
        CC, 2 * CC, HWSZ);

    // 4) fused im2col + 3x3 conv (M=216, K=1152) -> fp32 g_om
    hgemm_om<<<dim3(128, 2, BATCH), 256, SMEM_BYTES>>>(om_b, p_om);

    // 5) bilinear sample + mask -> fp16 interleaved g_Sh
    sample_kernel<<<(BATCH * DGRP * KPTS * HWSZ + 255) / 256, 256>>>();

    // 6) DCN GEMM + relu + bias + feat_arm -> out
    hgemm<2><<<dim3(HWSZ / 128, 1, BATCH), 256, SMEM_BYTES>>>(
        p_dcnwh, KBIG, 0,
        (const unsigned int*)p_Sh, (size_t)(KBIG / 2) * HWSZ,
        dcn_b,
        out, (size_t)CC * HWSZ,
        nullptr, 0,
        p_cat, (size_t)2 * CC * HWSZ,
        CC, KBIG, HWSZ);
}

// round 11
// speedup vs baseline: 1.0684x; 1.0136x over previous
#include <cuda_runtime.h>
#include <cuda_fp16.h>
#include <cstdint>
#include <stdint.h>
#include <math.h>

// ---------------- problem constants ----------------
#define BATCH 2
#define CC    128
#define HWSZ  16384         // 128*128
#define HS    64
#define DGRP  8
#define CG    16
#define KPTS  9
#define OMCH  216           // DG*3*KK
#define KBIG  1152          // CC*9

// ---------------- scratch ----------------
__device__ float g_pooled[BATCH * CC];
__device__ float g_scale [BATCH * CC];
__device__ float g_cat   [(size_t)BATCH * 2 * CC * HWSZ];     // fp32 feat_arm rows 0..127 (upper half unused now)
__device__ float g_om    [(size_t)BATCH * OMCH * HWSZ];       // fp32 offsets/mask

__device__ __align__(16) __half g_armWh[BATCH * CC * CC];
__device__ __align__(16) __half g_offwh[CC * 2 * CC];
__device__ __align__(16) __half g_omwh [OMCH * KBIG];
__device__ __align__(16) __half g_dcnwh[CC * KBIG];

// fp16 B operands, k-pair-interleaved word layout: word[kp][n] = (half(2kp,n), half(2kp+1,n))
__device__ __align__(16) __half g_flh  [(size_t)BATCH * CC * HWSZ];
__device__ __align__(16) __half g_cath [(size_t)BATCH * 2 * CC * HWSZ];
__device__ __align__(16) __half g_Sh   [(size_t)BATCH * KBIG * HWSZ];
// THREE pre-shifted fp16 copies of off_feat: copy ci (dx=ci-1): copy[ci][b][c][h][x] = off[b][c][h][x+dx]
__device__ __align__(16) __half g_offh3[(size_t)3 * BATCH * CC * HWSZ];

// ---------------- small kernels ----------------
__global__ void pool_kernel(const float* __restrict__ x) {
    int bc = blockIdx.x;
    const float4* p = (const float4*)(x + (size_t)bc * HWSZ);
    float s = 0.f;
    for (int i = threadIdx.x; i < HWSZ / 4; i += 256) {
        float4 v = p[i];
        s += v.x + v.y + v.z + v.w;
    }
    __shared__ float sh[256];
    sh[threadIdx.x] = s;
    __syncthreads();
    for (int o = 128; o > 0; o >>= 1) {
        if (threadIdx.x < o) sh[threadIdx.x] += sh[threadIdx.x + o];
        __syncthreads();
    }
    if (threadIdx.x == 0) g_pooled[bc] = sh[0] * (1.0f / HWSZ);
}

__global__ void atten_kernel(const float* __restrict__ aw, const float* __restrict__ ab,
                             const float* __restrict__ bg, const float* __restrict__ bb,
                             const float* __restrict__ bm, const float* __restrict__ bv) {
    int t = threadIdx.x;
    int b = t >> 7, o = t & 127;
    float a = ab[o];
    const float* pr = g_pooled + b * CC;
    const float* wr = aw + o * CC;
    #pragma unroll 4
    for (int c = 0; c < CC; c++) a += pr[c] * wr[c];
    a = (a - bm[o]) * rsqrtf(bv[o] + 1e-5f) * bg[o] + bb[o];
    g_scale[t] = 1.f + 1.f / (1.f + expf(-a));
}

__global__ void armw_kernel(const float* __restrict__ fsm_w) {
    int i = blockIdx.x * blockDim.x + threadIdx.x;
    int c = i & 127;
    int bo = i >> 7;
    int o = bo & 127;
    int b = bo >> 7;
    g_armWh[i] = __float2half(fsm_w[o * CC + c] * g_scale[b * CC + c]);
}

// weight packing + zero the never-written edge columns of g_offh3
__global__ void whpack_kernel(const float* __restrict__ om_w,
                              const float* __restrict__ dcn_w,
                              const float* __restrict__ off_w) {
    int i = blockIdx.x * blockDim.x + threadIdx.x;
    if (i < OMCH * KBIG) g_omwh[i] = __float2half(om_w[i]);
    if (i < CC * KBIG)   g_dcnwh[i] = __float2half(dcn_w[i]);
    if (i < CC * 2 * CC) g_offwh[i] = __float2half(off_w[i]);
    if (i < 2 * BATCH * CC * 128) {
        int e = i & 1;
        int t = i >> 1;
        int h = t & 127; t >>= 7;
        int c = t & 127; t >>= 7;
        int b = t & 1;
        int ci = e ? 2 : 0;
        int x  = e ? 127 : 0;
        g_offh3[(((size_t)ci * BATCH + b) * CC + c) * HWSZ + h * 128 + x] = __float2half(0.f);
    }
}

// fused (channel-pair vectorized): feat_l -> fp16 interleaved ; upsample feat_s -> fp16 interleaved.
// Dead fp32 feat_up store removed (sample reads g_cath only).
__global__ void prep2_kernel(const float* __restrict__ fl, const float* __restrict__ fs) {
    int i = blockIdx.x * blockDim.x + threadIdx.x;   // (b, cp, n)
    if (i >= BATCH * (CC / 2) * HWSZ) return;
    int n = i & (HWSZ - 1);
    int bcp = i >> 14;
    int b = bcp >> 6, cp = bcp & 63;

    const float* fl0 = fl + ((size_t)b * CC + 2 * cp) * HWSZ + n;
    *(__half2*)&g_flh[(((size_t)b * (CC / 2) + cp) * HWSZ + n) * 2] =
        __floats2half2_rn(fl0[0], fl0[HWSZ]);

    int h = n >> 7, w = n & 127;
    float fy = (h * 63.0f) / 127.0f;
    float fx = (w * 63.0f) / 127.0f;
    int y0 = (int)floorf(fy); float wy = fy - y0; int y1 = min(y0 + 1, 63);
    int x0 = (int)floorf(fx); float wx = fx - x0; int x1 = min(x0 + 1, 63);
    float w00 = (1.f - wy) * (1.f - wx), w01 = (1.f - wy) * wx;
    float w10 = wy * (1.f - wx), w11 = wy * wx;
    const float* p0 = fs + ((size_t)b * CC + 2 * cp) * (HS * HS);
    const float* p1 = p0 + HS * HS;
    float v0 = p0[y0 * HS + x0] * w00 + p0[y0 * HS + x1] * w01
             + p0[y1 * HS + x0] * w10 + p0[y1 * HS + x1] * w11;
    float v1 = p1[y0 * HS + x0] * w00 + p1[y0 * HS + x1] * w01
             + p1[y1 * HS + x0] * w10 + p1[y1 * HS + x1] * w11;
    *(__half2*)&g_cath[(((size_t)b * CC + (CC >> 1) + cp) * HWSZ + n) * 2] =
        __floats2half2_rn(v0, v1);
}

// bilinear sample + mask -> fp16 interleaved g_Sh ; corners read as fp16 channel-pair words
__global__ void sample_kernel() {
    int i = blockIdx.x * blockDim.x + threadIdx.x;
    if (i >= BATCH * DGRP * KPTS * HWSZ) return;
    int n = i & (HWSZ - 1);
    int t = i >> 14;
    int k = t % KPTS; t /= KPTS;
    int g = t & 7;
    int b = t >> 3;
    int h = n >> 7, w = n & 127;

    const float* om = g_om + (size_t)b * OMCH * HWSZ;
    int gk = g * KPTS + k;
    float offy = om[(size_t)gk * HWSZ + n];
    float offx = om[(size_t)(72 + gk) * HWSZ + n];
    float mm   = om[(size_t)(144 + gk) * HWSZ + n];
    mm = 1.f / (1.f + expf(-mm));

    float py = (float)(h + k / 3 - 1) + offy;
    float px = (float)(w + k % 3 - 1) + offx;
    float y0f = floorf(py), x0f = floorf(px);
    float ly = py - y0f, lx = px - x0f;
    int y0 = (int)y0f, x0 = (int)x0f;
    int y1 = y0 + 1, x1 = x0 + 1;
    bool vy0 = (y0 >= 0 && y0 < 128), vy1 = (y1 >= 0 && y1 < 128);
    bool vx0 = (x0 >= 0 && x0 < 128), vx1 = (x1 >= 0 && x1 < 128);
    int cy0 = min(max(y0, 0), 127), cy1 = min(max(y1, 0), 127);
    int cx0 = min(max(x0, 0), 127), cx1 = min(max(x1, 0), 127);
    float w00 = (vy0 && vx0) ? (1.f - ly) * (1.f - lx) * mm : 0.f;
    float w01 = (vy0 && vx1) ? (1.f - ly) * lx * mm : 0.f;
    float w10 = (vy1 && vx0) ? ly * (1.f - lx) * mm : 0.f;
    float w11 = (vy1 && vx1) ? ly * lx * mm : 0.f;
    int i00 = (cy0 << 7) + cx0, i01 = (cy0 << 7) + cx1;
    int i10 = (cy1 << 7) + cx0, i11 = (cy1 << 7) + cx1;

    const unsigned int* cw = (const unsigned int*)g_cath + (size_t)b * CC * HWSZ;
    #pragma unroll
    for (int cp = 0; cp < 8; cp++) {
        const unsigned int* rowp = cw + (size_t)(64 + g * 8 + cp) * HWSZ;
        float2 c00 = __half22float2(*(const __half2*)&rowp[i00]);
        float2 c01 = __half22float2(*(const __half2*)&rowp[i01]);
        float2 c10 = __half22float2(*(const __half2*)&rowp[i10]);
        float2 c11 = __half22float2(*(const __half2*)&rowp[i11]);
        float ve = w00 * c00.x + w01 * c01.x + w10 * c10.x + w11 * c11.x;
        float vo = w00 * c00.y + w01 * c01.y + w10 * c10.y + w11 * c11.y;
        int re = g * 144 + (2 * cp) * 9 + k;
        int ro = re + 9;
        g_Sh[((size_t)b * (KBIG / 2) + (re >> 1)) * (2 * HWSZ) + n * 2 + (re & 1)] = __float2half(ve);
        g_Sh[((size_t)b * (KBIG / 2) + (ro >> 1)) * (2 * HWSZ) + n * 2 + (ro & 1)] = __float2half(vo);
    }
}

// ---------------- FP16 tensor-core GEMM ----------------
#define AHSTR 40
#define BWSTR 136
#define A_STG (128 * AHSTR)
#define B_STG (16 * BWSTR)
#define SMEM_BYTES (3 * (A_STG * 2 + B_STG * 4))

#define HGEMM_CORE(MT)                                                                      \
    {                                                                                       \
    const unsigned int abase = (unsigned int)__cvta_generic_to_shared(                      \
        Asm + (size_t)cur * A_STG);                                                         \
    const unsigned int* bw = Bsm + (size_t)cur * B_STG;                                     \
    const int l15 = lane & 15, lhi8 = (lane >> 4) * 8;                                      \
    _Pragma("unroll")                                                                       \
    for (int ks = 0; ks < 2; ks++) {                                                        \
        unsigned int af[MT][4], bf[4][2];                                                   \
        _Pragma("unroll")                                                                   \
        for (int mi = 0; mi < MT; mi++) {                                                   \
            unsigned int aaddr = abase +                                                    \
                ((unsigned int)((wm + mi * 16 + l15) * AHSTR + ks * 16 + lhi8) << 1);       \
            asm volatile(                                                                   \
                "ldmatrix.sync.aligned.m8n8.x4.shared.b16 {%0,%1,%2,%3}, [%4];\n"           \
                : "=r"(af[mi][0]), "=r"(af[mi][1]), "=r"(af[mi][2]), "=r"(af[mi][3])        \
                : "r"(aaddr));                                                              \
        }                                                                                   \
        _Pragma("unroll")                                                                   \
        for (int ni = 0; ni < 4; ni++) {                                                    \
            int col = wn + ni * 8 + gid;                                                    \
            bf[ni][0] = bw[(ks * 8 + tig) * BWSTR + col];                                   \
            bf[ni][1] = bw[(ks * 8 + tig + 4) * BWSTR + col];                               \
        }                                                                                   \
        _Pragma("unroll")                                                                   \
        for (int mi = 0; mi < MT; mi++)                                                     \
            _Pragma("unroll")                                                               \
            for (int ni = 0; ni < 4; ni++) {                                                \
                asm volatile(                                                               \
                    "mma.sync.aligned.m16n8k16.row.col.f32.f16.f16.f32 "                    \
                    "{%0,%1,%2,%3}, {%4,%5,%6,%7}, {%8,%9}, {%0,%1,%2,%3};\n"               \
                    : "+f"(acc[mi][ni][0]), "+f"(acc[mi][ni][1]),                           \
                      "+f"(acc[mi][ni][2]), "+f"(acc[mi][ni][3])                            \
                    : "r"(af[mi][0]), "r"(af[mi][1]), "r"(af[mi][2]), "r"(af[mi][3]),       \
                      "r"(bf[ni][0]), "r"(bf[ni][1]));                                      \
            }                                                                               \
    }                                                                                       \
    }

template<int EPI>
__global__ __launch_bounds__(256, 2) void hgemm(
    const __half* __restrict__ A, int lda, size_t sA,
    const unsigned int* __restrict__ Bw, size_t sB,
    const float* __restrict__ bias,
    float* __restrict__ C, size_t sC,
    __half* __restrict__ Ch, size_t sCh,
    const float* __restrict__ Add, size_t sAdd,
    int M, int K, int N)
{
    const int bz = blockIdx.z;
    A += (size_t)bz * sA;
    Bw += (size_t)bz * sB;

    extern __shared__ __align__(16) char dsmem[];
    __half* Asm = (__half*)dsmem;
    unsigned int* Bsm = (unsigned int*)(dsmem + 3 * A_STG * 2);

    const int tid = threadIdx.x, lane = tid & 31, warp = tid >> 5;
    const int gid = lane >> 2, tig = lane & 3;
    const int wm = (warp >> 2) * 64, wn = (warp & 3) * 32;
    const int bm = blockIdx.y * 128, bn = blockIdx.x * 128;

    const int arow = tid >> 1, ac = (tid & 1) * 16;
    const __half* Ap = A + (size_t)(bm + arow) * lda + ac;
    const int apred = ((bm + arow) < M) ? 16 : 0;
    const int brow = tid >> 4, bcw = (tid & 15) * 8;
    const unsigned int* Bp = Bw + (size_t)brow * N + bn + bcw;

    float acc[4][4][4];
    #pragma unroll
    for (int mi = 0; mi < 4; mi++)
        #pragma unroll
        for (int ni = 0; ni < 4; ni++)
            #pragma unroll
            for (int q = 0; q < 4; q++) acc[mi][ni][q] = 0.f;

    const int nk = K >> 5;

    auto stage = [&](int kb, int buf) {
        unsigned int sa = (unsigned int)__cvta_generic_to_shared(Asm + (size_t)buf * A_STG + arow * AHSTR + ac);
        const __half* ga = Ap + kb * 32;
        asm volatile("cp.async.ca.shared.global [%0], [%1], 16, %2;\n" :: "r"(sa), "l"(ga), "r"(apred));
        asm volatile("cp.async.ca.shared.global [%0], [%1], 16, %2;\n" :: "r"(sa + 16), "l"(ga + 8), "r"(apred));
        unsigned int sb = (unsigned int)__cvta_generic_to_shared(Bsm + (size_t)buf * B_STG + brow * BWSTR + bcw);
        const unsigned int* gb = Bp + (size_t)kb * 16 * N;
        asm volatile("cp.async.cg.shared.global [%0], [%1], 16;\n" :: "r"(sb), "l"(gb));
        asm volatile("cp.async.cg.shared.global [%0], [%1], 16;\n" :: "r"(sb + 16), "l"(gb + 4));
        asm volatile("cp.async.commit_group;\n");
    };

    stage(0, 0);
    if (nk > 1) stage(1, 1);
    for (int kb = 0; kb < nk; kb++) {
        const int cur = kb % 3;
        if (kb + 1 < nk) { asm volatile("cp.async.wait_group 1;\n"); }
        else             { asm volatile("cp.async.wait_group 0;\n"); }
        __syncthreads();
        if (kb + 2 < nk) stage(kb + 2, (kb + 2) % 3);
        HGEMM_CORE(4);
    }

    #pragma unroll
    for (int mi = 0; mi < 4; mi++) {
        const int r0 = bm + wm + mi * 16 + gid;
        const int r1 = r0 + 8;
        const bool ok0 = r0 < M, ok1 = r1 < M;
        const float bv0 = (bias && ok0) ? bias[r0] : 0.f;
        const float bv1 = (bias && ok1) ? bias[r1] : 0.f;
        #pragma unroll
        for (int ni = 0; ni < 4; ni++) {
            const int cc = bn + wn + ni * 8 + 2 * tig;
            #pragma unroll
            for (int half_m = 0; half_m < 2; half_m++) {
                const int r = half_m ? r1 : r0;
                if (!(half_m ? ok1 : ok0)) continue;
                float v0 = acc[mi][ni][half_m * 2 + 0] + (half_m ? bv1 : bv0);
                float v1 = acc[mi][ni][half_m * 2 + 1] + (half_m ? bv1 : bv0);
                if (EPI == 2) {
                    size_t o = (size_t)bz * sC + (size_t)r * N + cc;
                    const float2 ad = *(const float2*)&Add[(size_t)bz * sAdd + (size_t)r * N + cc];
                    C[o] = fmaxf(v0, 0.f) + ad.x;
                    C[o + 1] = fmaxf(v1, 0.f) + ad.y;
                } else if (EPI == 3) {
                    size_t o = (size_t)bz * sC + (size_t)r * N + cc;
                    *(float2*)&C[o] = make_float2(v0, v1);
                    size_t oh = (size_t)bz * sCh + ((size_t)(r >> 1) * N + cc) * 2 + (r & 1);
                    Ch[oh] = __float2half(v0);
                    Ch[oh + 2] = __float2half(v1);
                } else if (EPI == 6) {
                    const int w = cc & 127;
                    const __half h0 = __float2half(v0), h1 = __float2half(v1);
                    const size_t rowoff = (size_t)r * HWSZ + (size_t)(cc & ~127);
                    __half* c0 = g_offh3 + ((size_t)0 * BATCH + bz) * CC * HWSZ + rowoff;
                    __half* c1 = g_offh3 + ((size_t)1 * BATCH + bz) * CC * HWSZ + rowoff;
                    __half* c2 = g_offh3 + ((size_t)2 * BATCH + bz) * CC * HWSZ + rowoff;
                    *(__half2*)&c1[w] = __halves2half2(h0, h1);
                    c0[w + 1] = h0;
                    if (w + 2 < 128) c0[w + 2] = h1;
                    if (w > 0) c2[w - 1] = h0;
                    c2[w] = h1;
                }
            }
        }
    }
}

// ---------------- fused im2col + fp16 GEMM for the 3x3 offset/mask conv ----------------
// MT m16-tiles per warp; block covers 2*MT*16 rows starting at bmofs.
template<int MT>
__global__ __launch_bounds__(256, 2) void hgemm_om(
    const float* __restrict__ bias, float* __restrict__ C, int bmofs)
{
    const int bz = blockIdx.z;
    const __half* A = g_omwh;
    float* Cb = C + (size_t)bz * OMCH * HWSZ;

    extern __shared__ __align__(16) char dsmem[];
    __half* Asm = (__half*)dsmem;
    unsigned int* Bsm = (unsigned int*)(dsmem + 3 * A_STG * 2);

    const int tid = threadIdx.x, lane = tid & 31, warp = tid >> 5;
    const int gid = lane >> 2, tig = lane & 3;
    const int wm = (warp >> 2) * (MT * 16), wn = (warp & 3) * 32;
    const int bm = bmofs;
    const int h = blockIdx.x;
    const int bn = h * 128;

    const int arow = tid >> 1, ac = (tid & 1) * 16;
    const __half* Ap = A + (size_t)(bm + arow) * KBIG + ac;
    const int apred = ((bm + arow) < OMCH) ? 16 : 0;

    const int kp = tid >> 4;
    const int chunk = tid & 15;

    float acc[MT][4][4];
    #pragma unroll
    for (int mi = 0; mi < MT; mi++)
        #pragma unroll
        for (int ni = 0; ni < 4; ni++)
            #pragma unroll
            for (int q = 0; q < 4; q++) acc[mi][ni][q] = 0.f;

    const int nk = KBIG / 32;   // 36
    uint4 bva, bvb;

    auto load_a = [&](int kb, int buf) {
        unsigned int sa = (unsigned int)__cvta_generic_to_shared(Asm + (size_t)buf * A_STG + arow * AHSTR + ac);
        const __half* ga = Ap + kb * 32;
        asm volatile("cp.async.ca.shared.global [%0], [%1], 16, %2;\n" :: "r"(sa), "l"(ga), "r"(apred));
        asm volatile("cp.async.ca.shared.global [%0], [%1], 16, %2;\n" :: "r"(sa + 16), "l"(ga + 8), "r"(apred));
        asm volatile("cp.async.commit_group;\n");
    };
    auto load_b_regs = [&](int kb) {
        #pragma unroll
        for (int rr = 0; rr < 2; rr++) {
            int ck = kb * 32 + 2 * kp + rr;
            int c  = ck / 9;
            int kk = ck - 9 * c;
            int dy = kk / 3 - 1;
            int ci = kk - (kk / 3) * 3;
            int hs = h + dy;
            uint4 v = make_uint4(0u, 0u, 0u, 0u);
            if ((unsigned)hs < 128u) {
                const __half* src = g_offh3 + (((size_t)ci * BATCH + bz) * CC + c) * HWSZ
                                  + hs * 128 + chunk * 8;
                v = *(const uint4*)src;
            }
            if (rr == 0) bva = v; else bvb = v;
        }
    };
    auto sts_b = [&](int buf) {
        unsigned int* dst = Bsm + (size_t)buf * B_STG + kp * BWSTR + chunk * 8;
        uint4 o1, o2;
        o1.x = __byte_perm(bva.x, bvb.x, 0x5410);
        o1.y = __byte_perm(bva.x, bvb.x, 0x7632);
        o1.z = __byte_perm(bva.y, bvb.y, 0x5410);
        o1.w = __byte_perm(bva.y, bvb.y, 0x7632);
        o2.x = __byte_perm(bva.z, bvb.z, 0x5410);
        o2.y = __byte_perm(bva.z, bvb.z, 0x7632);
        o2.z = __byte_perm(bva.w, bvb.w, 0x5410);
        o2.w = __byte_perm(bva.w, bvb.w, 0x7632);
        *(uint4*)dst = o1;
        *(uint4*)(dst + 4) = o2;
    };

    load_a(0, 0);
    load_b_regs(0);
    asm volatile("cp.async.wait_group 0;\n");
    sts_b(0);
    __syncthreads();

    for (int kb = 0; kb < nk; kb++) {
        const int cur = kb % 3;
        if (kb + 1 < nk) {
            load_a(kb + 1, (kb + 1) % 3);
            load_b_regs(kb + 1);
        }
        HGEMM_CORE(MT);
        if (kb + 1 < nk) {
            asm volatile("cp.async.wait_group 0;\n");
            sts_b((kb + 1) % 3);
        }
        __syncthreads();
    }

    #pragma unroll
    for (int mi = 0; mi < MT; mi++) {
        const int r0 = bm + wm + mi * 16 + gid;
        const int r1 = r0 + 8;
        const bool ok0 = r0 < OMCH, ok1 = r1 < OMCH;
        const float bv0 = ok0 ? bias[r0] : 0.f;
        const float bv1 = ok1 ? bias[r1] : 0.f;
        #pragma unroll
        for (int ni = 0; ni < 4; ni++) {
            const int cc = bn + wn + ni * 8 + 2 * tig;
            if (ok0) {
                size_t o = (size_t)r0 * HWSZ + cc;
                *(float2*)&Cb[o] = make_float2(acc[mi][ni][0] + bv0, acc[mi][ni][1] + bv0);
            }
            if (ok1) {
                size_t o = (size_t)r1 * HWSZ + cc;
                *(float2*)&Cb[o] = make_float2(acc[mi][ni][2] + bv1, acc[mi][ni][3] + bv1);
            }
        }
    }
}

// ---------------- launch ----------------
extern "C" void kernel_launch(void* const* d_in, const int* in_sizes, int n_in,
                              void* d_out, int out_size) {
    const float* feat_l  = (const float*)d_in[0];
    const float* feat_s  = (const float*)d_in[1];
    const float* atten_w = (const float*)d_in[2];
    const float* atten_b = (const float*)d_in[3];
    const float* bn_g    = (const float*)d_in[4];
    const float* bn_b    = (const float*)d_in[5];
    const float* bn_m    = (const float*)d_in[6];
    const float* bn_v    = (const float*)d_in[7];
    const float* fsm_w   = (const float*)d_in[8];
    const float* fsm_b   = (const float*)d_in[9];
    const float* om_b    = (const float*)d_in[12];
    const float* dcn_b   = (const float*)d_in[14];
    float* out = (float*)d_out;

    float *p_cat, *p_om;
    __half *p_armWh, *p_offwh, *p_dcnwh, *p_flh, *p_cath, *p_Sh;
    cudaGetSymbolAddress((void**)&p_cat,   g_cat);
    cudaGetSymbolAddress((void**)&p_om,    g_om);
    cudaGetSymbolAddress((void**)&p_armWh, g_armWh);
    cudaGetSymbolAddress((void**)&p_offwh, g_offwh);
    cudaGetSymbolAddress((void**)&p_dcnwh, g_dcnwh);
    cudaGetSymbolAddress((void**)&p_flh,   g_flh);
    cudaGetSymbolAddress((void**)&p_cath,  g_cath);
    cudaGetSymbolAddress((void**)&p_Sh,    g_Sh);

    cudaFuncSetAttribute(hgemm<2>, cudaFuncAttributeMaxDynamicSharedMemorySize, SMEM_BYTES);
    cudaFuncSetAttribute(hgemm<3>, cudaFuncAttributeMaxDynamicSharedMemorySize, SMEM_BYTES);
    cudaFuncSetAttribute(hgemm<6>, cudaFuncAttributeMaxDynamicSharedMemorySize, SMEM_BYTES);
    cudaFuncSetAttribute(hgemm_om<4>, cudaFuncAttributeMaxDynamicSharedMemorySize, SMEM_BYTES);
    cudaFuncSetAttribute(hgemm_om<3>, cudaFuncAttributeMaxDynamicSharedMemorySize, SMEM_BYTES);

    // 1) SE gate + weight packing (+ offh3 edge zeroing) + prep
    pool_kernel<<<BATCH * CC, 256>>>(feat_l);
    atten_kernel<<<1, 256>>>(atten_w, atten_b, bn_g, bn_b, bn_m, bn_v);
    armw_kernel<<<128, 256>>>(fsm_w);
    whpack_kernel<<<(OMCH * KBIG + 255) / 256, 256>>>(
        (const float*)d_in[11], (const float*)d_in[13], (const float*)d_in[10]);
    prep2_kernel<<<(BATCH * (CC / 2) * HWSZ + 255) / 256, 256>>>(feat_l, feat_s);

    // 2) feat_arm = armW @ feat_l + fsm_b -> fp32 g_cat rows 0..127 + fp16 g_cath kp 0..63
    hgemm<3><<<dim3(HWSZ / 128, 1, BATCH), 256, SMEM_BYTES>>>(
        p_armWh, CC, (size_t)CC * CC,
        (const unsigned int*)p_flh, (size_t)(CC / 2) * HWSZ,
        fsm_b,
        p_cat, (size_t)2 * CC * HWSZ,
        p_cath, (size_t)2 * CC * HWSZ,
        nullptr, 0,
        CC, CC, HWSZ);

    // 3) off_feat = off_w @ [feat_arm; feat_up] -> 3 shifted fp16 copies g_offh3
    hgemm<6><<<dim3(HWSZ / 128, 1, BATCH), 256, SMEM_BYTES>>>(
        p_offwh, 2 * CC, 0,
        (const unsigned int*)p_cath, (size_t)CC * HWSZ,
        nullptr,
        nullptr, 0,
        nullptr, 0,
        nullptr, 0,
        CC, 2 * CC, HWSZ);

    // 4) fused im2col + 3x3 conv: rows 0..127 (MT=4) and 128..215 (MT=3, 96 rows)
    hgemm_om<4><<<dim3(128, 1, BATCH), 256, SMEM_BYTES>>>(om_b, p_om, 0);
    hgemm_om<3><<<dim3(128, 1, BATCH), 256, SMEM_BYTES>>>(om_b, p_om, 128);

    // 5) bilinear sample + mask -> fp16 interleaved g_Sh
    sample_kernel<<<(BATCH * DGRP * KPTS * HWSZ + 255) / 256, 256>>>();

    // 6) DCN GEMM + relu + bias + feat_arm -> out
    hgemm<2><<<dim3(HWSZ / 128, 1, BATCH), 256, SMEM_BYTES>>>(
        p_dcnwh, KBIG, 0,
        (const unsigned int*)p_Sh, (size_t)(KBIG / 2) * HWSZ,
        dcn_b,
        out, (size_t)CC * HWSZ,
        nullptr, 0,
        p_cat, (size_t)2 * CC * HWSZ,
        CC, KBIG, HWSZ);
}

// round 12
// speedup vs baseline: 1.1096x; 1.0386x over previous
#include <cuda_runtime.h>
#include <cuda_fp16.h>
#include <cstdint>
#include <stdint.h>
#include <math.h>

// ---------------- problem constants ----------------
#define BATCH 2
#define CC    128
#define HWSZ  16384         // 128*128
#define HS    64
#define DGRP  8
#define CG    16
#define KPTS  9
#define OMCH  216           // DG*3*KK
#define KBIG  1152          // CC*9

// ---------------- scratch ----------------
__device__ float g_pooled[BATCH * CC];
__device__ float g_scale [BATCH * CC];
__device__ float g_cat   [(size_t)BATCH * 2 * CC * HWSZ];     // fp32 feat_arm rows 0..127
__device__ float g_om    [(size_t)BATCH * OMCH * HWSZ];       // fp32 offsets/mask

__device__ __align__(16) __half g_offwh[CC * 2 * CC];
__device__ __align__(16) __half g_omwh [OMCH * KBIG];
__device__ __align__(16) __half g_dcnwh[CC * KBIG];

// fp16 B operands
__device__ __align__(16) __half g_flh  [(size_t)BATCH * CC * HWSZ];       // k-pair interleaved
__device__ __align__(16) __half g_cath [(size_t)BATCH * 2 * CC * HWSZ];   // k-pair interleaved
__device__ __align__(16) __half g_Sh2  [(size_t)BATCH * KBIG * HWSZ];     // PLAIN [r][n] layout
// THREE pre-shifted fp16 copies of off_feat: copy ci (dx=ci-1)
__device__ __align__(16) __half g_offh3[(size_t)3 * BATCH * CC * HWSZ];

// ---------------- small kernels ----------------
__global__ void pool_kernel(const float* __restrict__ x) {
    int bc = blockIdx.x;
    const float4* p = (const float4*)(x + (size_t)bc * HWSZ);
    float s = 0.f;
    for (int i = threadIdx.x; i < HWSZ / 4; i += 256) {
        float4 v = p[i];
        s += v.x + v.y + v.z + v.w;
    }
    __shared__ float sh[256];
    sh[threadIdx.x] = s;
    __syncthreads();
    for (int o = 128; o > 0; o >>= 1) {
        if (threadIdx.x < o) sh[threadIdx.x] += sh[threadIdx.x + o];
        __syncthreads();
    }
    if (threadIdx.x == 0) g_pooled[bc] = sh[0] * (1.0f / HWSZ);
}

__global__ void atten_kernel(const float* __restrict__ aw, const float* __restrict__ ab,
                             const float* __restrict__ bg, const float* __restrict__ bb,
                             const float* __restrict__ bm, const float* __restrict__ bv) {
    int t = threadIdx.x;
    int b = t >> 7, o = t & 127;
    float a = ab[o];
    const float* pr = g_pooled + b * CC;
    const float* wr = aw + o * CC;
    #pragma unroll 4
    for (int c = 0; c < CC; c++) a += pr[c] * wr[c];
    a = (a - bm[o]) * rsqrtf(bv[o] + 1e-5f) * bg[o] + bb[o];
    g_scale[t] = 1.f + 1.f / (1.f + expf(-a));
}

// prep: feat_l->fp16 interleaved, upsample->fp16 interleaved, + absorbed whpack + edge zeroing
__global__ void prep2_kernel(const float* __restrict__ fl, const float* __restrict__ fs,
                             const float* __restrict__ om_w, const float* __restrict__ dcn_w,
                             const float* __restrict__ off_w) {
    int i = blockIdx.x * blockDim.x + threadIdx.x;   // (b, cp, n)
    if (i >= BATCH * (CC / 2) * HWSZ) return;

    // absorbed whpack (first 248832 threads do extra weight conversion)
    if (i < OMCH * KBIG) g_omwh[i] = __float2half(om_w[i]);
    if (i < CC * KBIG)   g_dcnwh[i] = __float2half(dcn_w[i]);
    if (i < CC * 2 * CC) g_offwh[i] = __float2half(off_w[i]);
    if (i < 2 * BATCH * CC * 128) {
        int e = i & 1;
        int t = i >> 1;
        int h = t & 127; t >>= 7;
        int c = t & 127; t >>= 7;
        int b = t & 1;
        int ci = e ? 2 : 0;
        int x  = e ? 127 : 0;
        g_offh3[(((size_t)ci * BATCH + b) * CC + c) * HWSZ + h * 128 + x] = __float2half(0.f);
    }

    int n = i & (HWSZ - 1);
    int bcp = i >> 14;
    int b = bcp >> 6, cp = bcp & 63;

    const float* fl0 = fl + ((size_t)b * CC + 2 * cp) * HWSZ + n;
    *(__half2*)&g_flh[(((size_t)b * (CC / 2) + cp) * HWSZ + n) * 2] =
        __floats2half2_rn(fl0[0], fl0[HWSZ]);

    int h = n >> 7, w = n & 127;
    float fy = (h * 63.0f) / 127.0f;
    float fx = (w * 63.0f) / 127.0f;
    int y0 = (int)floorf(fy); float wy = fy - y0; int y1 = min(y0 + 1, 63);
    int x0 = (int)floorf(fx); float wx = fx - x0; int x1 = min(x0 + 1, 63);
    float w00 = (1.f - wy) * (1.f - wx), w01 = (1.f - wy) * wx;
    float w10 = wy * (1.f - wx), w11 = wy * wx;
    const float* p0 = fs + ((size_t)b * CC + 2 * cp) * (HS * HS);
    const float* p1 = p0 + HS * HS;
    float v0 = p0[y0 * HS + x0] * w00 + p0[y0 * HS + x1] * w01
             + p0[y1 * HS + x0] * w10 + p0[y1 * HS + x1] * w11;
    float v1 = p1[y0 * HS + x0] * w00 + p1[y0 * HS + x1] * w01
             + p1[y1 * HS + x0] * w10 + p1[y1 * HS + x1] * w11;
    *(__half2*)&g_cath[(((size_t)b * CC + (CC >> 1) + cp) * HWSZ + n) * 2] =
        __floats2half2_rn(v0, v1);
}

// bilinear sample + mask -> PLAIN [r][n] fp16 g_Sh2 (coalesced stores)
__global__ void sample_kernel() {
    int i = blockIdx.x * blockDim.x + threadIdx.x;
    if (i >= BATCH * DGRP * KPTS * HWSZ) return;
    int n = i & (HWSZ - 1);
    int t = i >> 14;
    int k = t % KPTS; t /= KPTS;
    int g = t & 7;
    int b = t >> 3;
    int h = n >> 7, w = n & 127;

    const float* om = g_om + (size_t)b * OMCH * HWSZ;
    int gk = g * KPTS + k;
    float offy = om[(size_t)gk * HWSZ + n];
    float offx = om[(size_t)(72 + gk) * HWSZ + n];
    float mm   = om[(size_t)(144 + gk) * HWSZ + n];
    mm = 1.f / (1.f + expf(-mm));

    float py = (float)(h + k / 3 - 1) + offy;
    float px = (float)(w + k % 3 - 1) + offx;
    float y0f = floorf(py), x0f = floorf(px);
    float ly = py - y0f, lx = px - x0f;
    int y0 = (int)y0f, x0 = (int)x0f;
    int y1 = y0 + 1, x1 = x0 + 1;
    bool vy0 = (y0 >= 0 && y0 < 128), vy1 = (y1 >= 0 && y1 < 128);
    bool vx0 = (x0 >= 0 && x0 < 128), vx1 = (x1 >= 0 && x1 < 128);
    int cy0 = min(max(y0, 0), 127), cy1 = min(max(y1, 0), 127);
    int cx0 = min(max(x0, 0), 127), cx1 = min(max(x1, 0), 127);
    float w00 = (vy0 && vx0) ? (1.f - ly) * (1.f - lx) * mm : 0.f;
    float w01 = (vy0 && vx1) ? (1.f - ly) * lx * mm : 0.f;
    float w10 = (vy1 && vx0) ? ly * (1.f - lx) * mm : 0.f;
    float w11 = (vy1 && vx1) ? ly * lx * mm : 0.f;
    int i00 = (cy0 << 7) + cx0, i01 = (cy0 << 7) + cx1;
    int i10 = (cy1 << 7) + cx0, i11 = (cy1 << 7) + cx1;

    const unsigned int* cw = (const unsigned int*)g_cath + (size_t)b * CC * HWSZ;
    __half* Sb = g_Sh2 + (size_t)b * KBIG * HWSZ;
    #pragma unroll
    for (int cp = 0; cp < 8; cp++) {
        const unsigned int* rowp = cw + (size_t)(64 + g * 8 + cp) * HWSZ;
        float2 c00 = __half22float2(*(const __half2*)&rowp[i00]);
        float2 c01 = __half22float2(*(const __half2*)&rowp[i01]);
        float2 c10 = __half22float2(*(const __half2*)&rowp[i10]);
        float2 c11 = __half22float2(*(const __half2*)&rowp[i11]);
        float ve = w00 * c00.x + w01 * c01.x + w10 * c10.x + w11 * c11.x;
        float vo = w00 * c00.y + w01 * c01.y + w10 * c10.y + w11 * c11.y;
        int re = g * 144 + (2 * cp) * 9 + k;
        Sb[(size_t)re * HWSZ + n] = __float2half(ve);
        Sb[(size_t)(re + 9) * HWSZ + n] = __float2half(vo);
    }
}

// ---------------- FP16 tensor-core GEMM ----------------
#define AHSTR 40
#define BWSTR 136
#define A_STG (128 * AHSTR)
#define B_STG (16 * BWSTR)
#define SMEM_BYTES (3 * (A_STG * 2 + B_STG * 4))

#define HGEMM_CORE(MT)                                                                      \
    {                                                                                       \
    const unsigned int abase = (unsigned int)__cvta_generic_to_shared(                      \
        Asm + (size_t)cur * A_STG);                                                         \
    const unsigned int* bw = Bsm + (size_t)cur * B_STG;                                     \
    const int l15 = lane & 15, lhi8 = (lane >> 4) * 8;                                      \
    _Pragma("unroll")                                                                       \
    for (int ks = 0; ks < 2; ks++) {                                                        \
        unsigned int af[MT][4], bf[4][2];                                                   \
        _Pragma("unroll")                                                                   \
        for (int mi = 0; mi < MT; mi++) {                                                   \
            unsigned int aaddr = abase +                                                    \
                ((unsigned int)((wm + mi * 16 + l15) * AHSTR + ks * 16 + lhi8) << 1);       \
            asm volatile(                                                                   \
                "ldmatrix.sync.aligned.m8n8.x4.shared.b16 {%0,%1,%2,%3}, [%4];\n"           \
                : "=r"(af[mi][0]), "=r"(af[mi][1]), "=r"(af[mi][2]), "=r"(af[mi][3])        \
                : "r"(aaddr));                                                              \
        }                                                                                   \
        _Pragma("unroll")                                                                   \
        for (int ni = 0; ni < 4; ni++) {                                                    \
            int col = wn + ni * 8 + gid;                                                    \
            bf[ni][0] = bw[(ks * 8 + tig) * BWSTR + col];                                   \
            bf[ni][1] = bw[(ks * 8 + tig + 4) * BWSTR + col];                               \
        }                                                                                   \
        _Pragma("unroll")                                                                   \
        for (int mi = 0; mi < MT; mi++)                                                     \
            _Pragma("unroll")                                                               \
            for (int ni = 0; ni < 4; ni++) {                                                \
                asm volatile(                                                               \
                    "mma.sync.aligned.m16n8k16.row.col.f32.f16.f16.f32 "                    \
                    "{%0,%1,%2,%3}, {%4,%5,%6,%7}, {%8,%9}, {%0,%1,%2,%3};\n"               \
                    : "+f"(acc[mi][ni][0]), "+f"(acc[mi][ni][1]),                           \
                      "+f"(acc[mi][ni][2]), "+f"(acc[mi][ni][3])                            \
                    : "r"(af[mi][0]), "r"(af[mi][1]), "r"(af[mi][2]), "r"(af[mi][3]),       \
                      "r"(bf[ni][0]), "r"(bf[ni][1]));                                      \
            }                                                                               \
    }                                                                                       \
    }

// EPI 3: C=acc+bias fp32 AND interleaved fp16 Ch  (ARMW=1: A built on the fly from fp32 fsm_w * scale)
// EPI 6: off-GEMM -> 3 shifted fp16 copies
template<int EPI, int ARMW>
__global__ __launch_bounds__(256, 2) void hgemm(
    const __half* __restrict__ A, int lda, size_t sA,
    const unsigned int* __restrict__ Bw, size_t sB,
    const float* __restrict__ bias,
    float* __restrict__ C, size_t sC,
    __half* __restrict__ Ch, size_t sCh,
    const float* __restrict__ Scl,        // ARMW: per-batch channel scale (g_scale)
    int M, int K, int N)
{
    const int bz = blockIdx.z;
    A += (size_t)bz * sA;
    Bw += (size_t)bz * sB;

    extern __shared__ __align__(16) char dsmem[];
    __half* Asm = (__half*)dsmem;
    unsigned int* Bsm = (unsigned int*)(dsmem + 3 * A_STG * 2);

    const int tid = threadIdx.x, lane = tid & 31, warp = tid >> 5;
    const int gid = lane >> 2, tig = lane & 3;
    const int wm = (warp >> 2) * 64, wn = (warp & 3) * 32;
    const int bm = blockIdx.y * 128, bn = blockIdx.x * 128;

    const int arow = tid >> 1, ac = (tid & 1) * 16;
    const __half* Ap = A + (size_t)(bm + arow) * lda + ac;
    const int apred = ((bm + arow) < M) ? 16 : 0;
    const int brow = tid >> 4, bcw = (tid & 15) * 8;
    const unsigned int* Bp = Bw + (size_t)brow * N + bn + bcw;

    float acc[4][4][4];
    #pragma unroll
    for (int mi = 0; mi < 4; mi++)
        #pragma unroll
        for (int ni = 0; ni < 4; ni++)
            #pragma unroll
            for (int q = 0; q < 4; q++) acc[mi][ni][q] = 0.f;

    const int nk = K >> 5;

    auto stage = [&](int kb, int buf) {
        if (ARMW) {
            // A = fp32 fsm_w row * scale[c], converted to fp16, sync STS
            const float* gw = (const float*)A + (size_t)(bm + arow) * lda + kb * 32 + ac;
            const float* sc = Scl + bz * CC + kb * 32 + ac;
            __half hv[16];
            #pragma unroll
            for (int j = 0; j < 16; j += 4) {
                float4 w4 = *(const float4*)(gw + j);
                hv[j + 0] = __float2half(w4.x * sc[j + 0]);
                hv[j + 1] = __float2half(w4.y * sc[j + 1]);
                hv[j + 2] = __float2half(w4.z * sc[j + 2]);
                hv[j + 3] = __float2half(w4.w * sc[j + 3]);
            }
            __half* d = Asm + (size_t)buf * A_STG + arow * AHSTR + ac;
            *(uint4*)d = *(uint4*)hv;
            *(uint4*)(d + 8) = *(uint4*)(hv + 8);
        } else {
            unsigned int sa = (unsigned int)__cvta_generic_to_shared(Asm + (size_t)buf * A_STG + arow * AHSTR + ac);
            const __half* ga = Ap + kb * 32;
            asm volatile("cp.async.ca.shared.global [%0], [%1], 16, %2;\n" :: "r"(sa), "l"(ga), "r"(apred));
            asm volatile("cp.async.ca.shared.global [%0], [%1], 16, %2;\n" :: "r"(sa + 16), "l"(ga + 8), "r"(apred));
        }
        unsigned int sb = (unsigned int)__cvta_generic_to_shared(Bsm + (size_t)buf * B_STG + brow * BWSTR + bcw);
        const unsigned int* gb = Bp + (size_t)kb * 16 * N;
        asm volatile("cp.async.cg.shared.global [%0], [%1], 16;\n" :: "r"(sb), "l"(gb));
        asm volatile("cp.async.cg.shared.global [%0], [%1], 16;\n" :: "r"(sb + 16), "l"(gb + 4));
        asm volatile("cp.async.commit_group;\n");
    };

    stage(0, 0);
    if (nk > 1) stage(1, 1);
    if (ARMW) __syncthreads();   // make stage-0/1 sync A-STS visible before first consume
    for (int kb = 0; kb < nk; kb++) {
        const int cur = kb % 3;
        if (kb + 1 < nk) { asm volatile("cp.async.wait_group 1;\n"); }
        else             { asm volatile("cp.async.wait_group 0;\n"); }
        __syncthreads();
        if (kb + 2 < nk) stage(kb + 2, (kb + 2) % 3);
        if (ARMW && kb + 2 < nk) { /* STS for kb+2 visible after next iteration's sync */ }
        HGEMM_CORE(4);
    }

    #pragma unroll
    for (int mi = 0; mi < 4; mi++) {
        const int r0 = bm + wm + mi * 16 + gid;
        const int r1 = r0 + 8;
        const bool ok0 = r0 < M, ok1 = r1 < M;
        const float bv0 = (bias && ok0) ? bias[r0] : 0.f;
        const float bv1 = (bias && ok1) ? bias[r1] : 0.f;
        #pragma unroll
        for (int ni = 0; ni < 4; ni++) {
            const int cc = bn + wn + ni * 8 + 2 * tig;
            #pragma unroll
            for (int half_m = 0; half_m < 2; half_m++) {
                const int r = half_m ? r1 : r0;
                if (!(half_m ? ok1 : ok0)) continue;
                float v0 = acc[mi][ni][half_m * 2 + 0] + (half_m ? bv1 : bv0);
                float v1 = acc[mi][ni][half_m * 2 + 1] + (half_m ? bv1 : bv0);
                if (EPI == 3) {
                    size_t o = (size_t)bz * sC + (size_t)r * N + cc;
                    *(float2*)&C[o] = make_float2(v0, v1);
                    size_t oh = (size_t)bz * sCh + ((size_t)(r >> 1) * N + cc) * 2 + (r & 1);
                    Ch[oh] = __float2half(v0);
                    Ch[oh + 2] = __float2half(v1);
                } else if (EPI == 6) {
                    const int w = cc & 127;
                    const __half h0 = __float2half(v0), h1 = __float2half(v1);
                    const size_t rowoff = (size_t)r * HWSZ + (size_t)(cc & ~127);
                    __half* c0 = g_offh3 + ((size_t)0 * BATCH + bz) * CC * HWSZ + rowoff;
                    __half* c1 = g_offh3 + ((size_t)1 * BATCH + bz) * CC * HWSZ + rowoff;
                    __half* c2 = g_offh3 + ((size_t)2 * BATCH + bz) * CC * HWSZ + rowoff;
                    *(__half2*)&c1[w] = __halves2half2(h0, h1);
                    c0[w + 1] = h0;
                    if (w + 2 < 128) c0[w + 2] = h1;
                    if (w > 0) c2[w - 1] = h0;
                    c2[w] = h1;
                }
            }
        }
    }
}

// ---------------- reg-staged-B GEMMs (om conv + DCN) ----------------
// OM=1: B built from shifted off_feat copies (im2col); OM=0: B from plain g_Sh2 rows (DCN).
// MT m16-tiles per warp; EPI2D: relu+bias+Add epilogue (DCN) else plain bias (om).
template<int MT, int OM, int EPI2D>
__global__ __launch_bounds__(256, 2) void hgemm_rs(
    const __half* __restrict__ A,         // weights [M x KBIG]
    const float* __restrict__ bias,
    float* __restrict__ C, size_t sC,
    const float* __restrict__ Add, size_t sAdd,
    int bmofs, int M, int N)
{
    const int bz = blockIdx.z;
    float* Cb = C + (size_t)bz * sC;

    extern __shared__ __align__(16) char dsmem[];
    __half* Asm = (__half*)dsmem;
    unsigned int* Bsm = (unsigned int*)(dsmem + 3 * A_STG * 2);

    const int tid = threadIdx.x, lane = tid & 31, warp = tid >> 5;
    const int gid = lane >> 2, tig = lane & 3;
    const int wm = (warp >> 2) * (MT * 16), wn = (warp & 3) * 32;
    const int bm = bmofs;
    const int h = blockIdx.x;
    const int bn = h * 128;

    const int arow = tid >> 1, ac = (tid & 1) * 16;
    const __half* Ap = A + (size_t)(bm + arow) * KBIG + ac;
    const int apred = ((bm + arow) < M) ? 16 : 0;

    const int kp = tid >> 4;
    const int chunk = tid & 15;

    float acc[MT][4][4];
    #pragma unroll
    for (int mi = 0; mi < MT; mi++)
        #pragma unroll
        for (int ni = 0; ni < 4; ni++)
            #pragma unroll
            for (int q = 0; q < 4; q++) acc[mi][ni][q] = 0.f;

    const int nk = KBIG / 32;   // 36
    uint4 bva, bvb;

    auto load_a = [&](int kb, int buf) {
        unsigned int sa = (unsigned int)__cvta_generic_to_shared(Asm + (size_t)buf * A_STG + arow * AHSTR + ac);
        const __half* ga = Ap + kb * 32;
        asm volatile("cp.async.ca.shared.global [%0], [%1], 16, %2;\n" :: "r"(sa), "l"(ga), "r"(apred));
        asm volatile("cp.async.ca.shared.global [%0], [%1], 16, %2;\n" :: "r"(sa + 16), "l"(ga + 8), "r"(apred));
        asm volatile("cp.async.commit_group;\n");
    };
    auto load_b_regs = [&](int kb) {
        if (OM) {
            #pragma unroll
            for (int rr = 0; rr < 2; rr++) {
                int ck = kb * 32 + 2 * kp + rr;
                int c  = ck / 9;
                int kk = ck - 9 * c;
                int dy = kk / 3 - 1;
                int ci = kk - (kk / 3) * 3;
                int hs = h + dy;
                uint4 v = make_uint4(0u, 0u, 0u, 0u);
                if ((unsigned)hs < 128u) {
                    const __half* src = g_offh3 + (((size_t)ci * BATCH + bz) * CC + c) * HWSZ
                                      + hs * 128 + chunk * 8;
                    v = *(const uint4*)src;
                }
                if (rr == 0) bva = v; else bvb = v;
            }
        } else {
            const __half* s0 = g_Sh2 + (size_t)bz * KBIG * HWSZ
                             + (size_t)(kb * 32 + 2 * kp) * HWSZ + bn + chunk * 8;
            bva = *(const uint4*)s0;
            bvb = *(const uint4*)(s0 + HWSZ);
        }
    };
    auto sts_b = [&](int buf) {
        unsigned int* dst = Bsm + (size_t)buf * B_STG + kp * BWSTR + chunk * 8;
        uint4 o1, o2;
        o1.x = __byte_perm(bva.x, bvb.x, 0x5410);
        o1.y = __byte_perm(bva.x, bvb.x, 0x7632);
        o1.z = __byte_perm(bva.y, bvb.y, 0x5410);
        o1.w = __byte_perm(bva.y, bvb.y, 0x7632);
        o2.x = __byte_perm(bva.z, bvb.z, 0x5410);
        o2.y = __byte_perm(bva.z, bvb.z, 0x7632);
        o2.z = __byte_perm(bva.w, bvb.w, 0x5410);
        o2.w = __byte_perm(bva.w, bvb.w, 0x7632);
        *(uint4*)dst = o1;
        *(uint4*)(dst + 4) = o2;
    };

    load_a(0, 0);
    load_b_regs(0);
    asm volatile("cp.async.wait_group 0;\n");
    sts_b(0);
    __syncthreads();

    for (int kb = 0; kb < nk; kb++) {
        const int cur = kb % 3;
        if (kb + 1 < nk) {
            load_a(kb + 1, (kb + 1) % 3);
            load_b_regs(kb + 1);
        }
        HGEMM_CORE(MT);
        if (kb + 1 < nk) {
            asm volatile("cp.async.wait_group 0;\n");
            sts_b((kb + 1) % 3);
        }
        __syncthreads();
    }

    #pragma unroll
    for (int mi = 0; mi < MT; mi++) {
        const int r0 = bm + wm + mi * 16 + gid;
        const int r1 = r0 + 8;
        const bool ok0 = r0 < M, ok1 = r1 < M;
        const float bv0 = ok0 ? bias[r0] : 0.f;
        const float bv1 = ok1 ? bias[r1] : 0.f;
        #pragma unroll
        for (int ni = 0; ni < 4; ni++) {
            const int cc = bn + wn + ni * 8 + 2 * tig;
            #pragma unroll
            for (int half_m = 0; half_m < 2; half_m++) {
                const int r = half_m ? r1 : r0;
                if (!(half_m ? ok1 : ok0)) continue;
                float v0 = acc[mi][ni][half_m * 2 + 0] + (half_m ? bv1 : bv0);
                float v1 = acc[mi][ni][half_m * 2 + 1] + (half_m ? bv1 : bv0);
                size_t o = (size_t)r * HWSZ + cc;
                if (EPI2D) {
                    const float2 ad = *(const float2*)&Add[(size_t)bz * sAdd + o];
                    v0 = fmaxf(v0, 0.f) + ad.x;
                    v1 = fmaxf(v1, 0.f) + ad.y;
                }
                *(float2*)&Cb[o] = make_float2(v0, v1);
            }
        }
    }
}

// ---------------- launch ----------------
extern "C" void kernel_launch(void* const* d_in, const int* in_sizes, int n_in,
                              void* d_out, int out_size) {
    const float* feat_l  = (const float*)d_in[0];
    const float* feat_s  = (const float*)d_in[1];
    const float* atten_w = (const float*)d_in[2];
    const float* atten_b = (const float*)d_in[3];
    const float* bn_g    = (const float*)d_in[4];
    const float* bn_b    = (const float*)d_in[5];
    const float* bn_m    = (const float*)d_in[6];
    const float* bn_v    = (const float*)d_in[7];
    const float* fsm_w   = (const float*)d_in[8];
    const float* fsm_b   = (const float*)d_in[9];
    const float* om_b    = (const float*)d_in[12];
    const float* dcn_b   = (const float*)d_in[14];
    float* out = (float*)d_out;

    float *p_cat, *p_om, *p_scale;
    __half *p_offwh, *p_dcnwh, *p_omwh, *p_flh, *p_cath;
    cudaGetSymbolAddress((void**)&p_cat,   g_cat);
    cudaGetSymbolAddress((void**)&p_om,    g_om);
    cudaGetSymbolAddress((void**)&p_scale, g_scale);
    cudaGetSymbolAddress((void**)&p_offwh, g_offwh);
    cudaGetSymbolAddress((void**)&p_dcnwh, g_dcnwh);
    cudaGetSymbolAddress((void**)&p_omwh,  g_omwh);
    cudaGetSymbolAddress((void**)&p_flh,   g_flh);
    cudaGetSymbolAddress((void**)&p_cath,  g_cath);

    cudaFuncSetAttribute(hgemm<3, 1>, cudaFuncAttributeMaxDynamicSharedMemorySize, SMEM_BYTES);
    cudaFuncSetAttribute(hgemm<6, 0>, cudaFuncAttributeMaxDynamicSharedMemorySize, SMEM_BYTES);
    cudaFuncSetAttribute(hgemm_rs<4, 1, 0>, cudaFuncAttributeMaxDynamicSharedMemorySize, SMEM_BYTES);
    cudaFuncSetAttribute(hgemm_rs<3, 1, 0>, cudaFuncAttributeMaxDynamicSharedMemorySize, SMEM_BYTES);
    cudaFuncSetAttribute(hgemm_rs<4, 0, 1>, cudaFuncAttributeMaxDynamicSharedMemorySize, SMEM_BYTES);

    // 1) prep (+whpack +edge zero)
    prep2_kernel<<<(BATCH * (CC / 2) * HWSZ + 255) / 256, 256>>>(
        feat_l, feat_s,
        (const float*)d_in[11], (const float*)d_in[13], (const float*)d_in[10]);
    // 2-3) SE gate
    pool_kernel<<<BATCH * CC, 256>>>(feat_l);
    atten_kernel<<<1, 256>>>(atten_w, atten_b, bn_g, bn_b, bn_m, bn_v);

    // 4) feat_arm GEMM (A = fsm_w*scale built in-loader) -> fp32 g_cat + fp16 g_cath
    hgemm<3, 1><<<dim3(HWSZ / 128, 1, BATCH), 256, SMEM_BYTES>>>(
        (const __half*)fsm_w, CC, 0,
        (const unsigned int*)p_flh, (size_t)(CC / 2) * HWSZ,
        fsm_b,
        p_cat, (size_t)2 * CC * HWSZ,
        p_cath, (size_t)2 * CC * HWSZ,
        p_scale,
        CC, CC, HWSZ);

    // 5) off_feat GEMM -> 3 shifted fp16 copies g_offh3
    hgemm<6, 0><<<dim3(HWSZ / 128, 1, BATCH), 256, SMEM_BYTES>>>(
        p_offwh, 2 * CC, 0,
        (const unsigned int*)p_cath, (size_t)CC * HWSZ,
        nullptr,
        nullptr, 0,
        nullptr, 0,
        nullptr,
        CC, 2 * CC, HWSZ);

    // 6-7) fused im2col + 3x3 conv: rows 0..127 (MT=4) and 128..215 (MT=3)
    hgemm_rs<4, 1, 0><<<dim3(128, 1, BATCH), 256, SMEM_BYTES>>>(
        p_omwh, om_b, p_om, (size_t)OMCH * HWSZ, nullptr, 0, 0, OMCH, HWSZ);
    hgemm_rs<3, 1, 0><<<dim3(128, 1, BATCH), 256, SMEM_BYTES>>>(
        p_omwh, om_b, p_om, (size_t)OMCH * HWSZ, nullptr, 0, 128, OMCH, HWSZ);

    // 8) bilinear sample + mask -> plain [r][n] fp16 g_Sh2 (coalesced)
    sample_kernel<<<(BATCH * DGRP * KPTS * HWSZ + 255) / 256, 256>>>();

    // 9) DCN GEMM (reg-staged B from g_Sh2) + relu + bias + feat_arm -> out
    hgemm_rs<4, 0, 1><<<dim3(128, 1, BATCH), 256, SMEM_BYTES>>>(
        p_dcnwh, dcn_b, out, (size_t)CC * HWSZ,
        p_cat, (size_t)2 * CC * HWSZ, 0, CC, HWSZ);
}

// round 14
// speedup vs baseline: 1.1335x; 1.0216x over previous
#include <cuda_runtime.h>
#include <cuda_fp16.h>
#include <cstdint>
#include <stdint.h>
#include <math.h>

// ---------------- problem constants ----------------
#define BATCH 2
#define CC    128
#define HWSZ  16384         // 128*128
#define HS    64
#define DGRP  8
#define CG    16
#define KPTS  9
#define OMCH  216           // DG*3*KK
#define KBIG  1152          // CC*9

// ---------------- scratch ----------------
__device__ float g_pooled[BATCH * CC];
__device__ float g_scale [BATCH * CC];
__device__ float g_cat   [(size_t)BATCH * 2 * CC * HWSZ];     // fp32 feat_arm rows 0..127
__device__ float g_om    [(size_t)BATCH * OMCH * HWSZ];       // fp32 offsets/mask

__device__ __align__(16) __half g_offwh[CC * 2 * CC];
__device__ __align__(16) __half g_omwh [OMCH * KBIG];
__device__ __align__(16) __half g_dcnwh[CC * KBIG];

// fp16 operands, PLAIN k-major [row][n] layouts
__device__ __align__(16) __half g_flh  [(size_t)BATCH * CC * HWSZ];       // feat_l
__device__ __align__(16) __half g_cath [(size_t)BATCH * 2 * CC * HWSZ];   // rows 0-127 arm, 128-255 up
__device__ __align__(16) __half g_Sh2  [(size_t)BATCH * KBIG * HWSZ];     // sampled DCN input
// channel-pair interleaved words of feat_up ONLY (for sample gathers)
__device__ __align__(16) unsigned int g_upw[(size_t)BATCH * (CC / 2) * HWSZ];
// THREE pre-shifted fp16 copies of off_feat: copy ci (dx=ci-1)
__device__ __align__(16) __half g_offh3[(size_t)3 * BATCH * CC * HWSZ];

__device__ __forceinline__ unsigned int h2_as_u32(__half2 v) {
    return *(unsigned int*)&v;
}

// ---------------- small kernels ----------------
__global__ void pool_kernel(const float* __restrict__ x) {
    int bc = blockIdx.x;
    const float4* p = (const float4*)(x + (size_t)bc * HWSZ);
    float s = 0.f;
    for (int i = threadIdx.x; i < HWSZ / 4; i += 256) {
        float4 v = p[i];
        s += v.x + v.y + v.z + v.w;
    }
    __shared__ float sh[256];
    sh[threadIdx.x] = s;
    __syncthreads();
    for (int o = 128; o > 0; o >>= 1) {
        if (threadIdx.x < o) sh[threadIdx.x] += sh[threadIdx.x + o];
        __syncthreads();
    }
    if (threadIdx.x == 0) g_pooled[bc] = sh[0] * (1.0f / HWSZ);
}

__global__ void atten_kernel(const float* __restrict__ aw, const float* __restrict__ ab,
                             const float* __restrict__ bg, const float* __restrict__ bb,
                             const float* __restrict__ bm, const float* __restrict__ bv) {
    int t = threadIdx.x;
    int b = t >> 7, o = t & 127;
    float a = ab[o];
    const float* pr = g_pooled + b * CC;
    const float* wr = aw + o * CC;
    #pragma unroll 4
    for (int c = 0; c < CC; c++) a += pr[c] * wr[c];
    a = (a - bm[o]) * rsqrtf(bv[o] + 1e-5f) * bg[o] + bb[o];
    g_scale[t] = 1.f + 1.f / (1.f + expf(-a));
}

// prep: feat_l->fp16 plain, upsample->fp16 plain + interleaved words, + whpack + edge zeroing
__global__ void prep3_kernel(const float* __restrict__ fl, const float* __restrict__ fs,
                             const float* __restrict__ om_w, const float* __restrict__ dcn_w,
                             const float* __restrict__ off_w) {
    int i = blockIdx.x * blockDim.x + threadIdx.x;   // (b, cp, n)
    if (i >= BATCH * (CC / 2) * HWSZ) return;

    if (i < OMCH * KBIG) g_omwh[i] = __float2half(om_w[i]);
    if (i < CC * KBIG)   g_dcnwh[i] = __float2half(dcn_w[i]);
    if (i < CC * 2 * CC) g_offwh[i] = __float2half(off_w[i]);
    if (i < 2 * BATCH * CC * 128) {
        int e = i & 1;
        int t = i >> 1;
        int h = t & 127; t >>= 7;
        int c = t & 127; t >>= 7;
        int b = t & 1;
        int ci = e ? 2 : 0;
        int x  = e ? 127 : 0;
        g_offh3[(((size_t)ci * BATCH + b) * CC + c) * HWSZ + h * 128 + x] = __float2half(0.f);
    }

    int n = i & (HWSZ - 1);
    int bcp = i >> 14;
    int b = bcp >> 6, cp = bcp & 63;

    // feat_l plain fp16 (channels 2cp, 2cp+1)
    const float* fl0 = fl + ((size_t)b * CC + 2 * cp) * HWSZ + n;
    size_t flo = ((size_t)b * CC + 2 * cp) * HWSZ + n;
    g_flh[flo] = __float2half(fl0[0]);
    g_flh[flo + HWSZ] = __float2half(fl0[HWSZ]);

    // upsample channels 2cp, 2cp+1 at n
    int h = n >> 7, w = n & 127;
    float fy = (h * 63.0f) / 127.0f;
    float fx = (w * 63.0f) / 127.0f;
    int y0 = (int)floorf(fy); float wy = fy - y0; int y1 = min(y0 + 1, 63);
    int x0 = (int)floorf(fx); float wx = fx - x0; int x1 = min(x0 + 1, 63);
    float w00 = (1.f - wy) * (1.f - wx), w01 = (1.f - wy) * wx;
    float w10 = wy * (1.f - wx), w11 = wy * wx;
    const float* p0 = fs + ((size_t)b * CC + 2 * cp) * (HS * HS);
    const float* p1 = p0 + HS * HS;
    float v0 = p0[y0 * HS + x0] * w00 + p0[y0 * HS + x1] * w01
             + p0[y1 * HS + x0] * w10 + p0[y1 * HS + x1] * w11;
    float v1 = p1[y0 * HS + x0] * w00 + p1[y0 * HS + x1] * w01
             + p1[y1 * HS + x0] * w10 + p1[y1 * HS + x1] * w11;
    __half h0 = __float2half(v0), h1 = __float2half(v1);
    // interleaved word for sample gathers
    g_upw[((size_t)b * (CC / 2) + cp) * HWSZ + n] = h2_as_u32(__halves2half2(h0, h1));
    // plain rows for the off GEMM B (rows 128+2cp, 128+2cp+1)
    size_t co = ((size_t)b * 2 * CC + CC + 2 * cp) * HWSZ + n;
    g_cath[co] = h0;
    g_cath[co + HWSZ] = h1;
}

// bilinear sample + mask -> plain [r][n] fp16 g_Sh2
__global__ void sample_kernel() {
    int i = blockIdx.x * blockDim.x + threadIdx.x;
    if (i >= BATCH * DGRP * KPTS * HWSZ) return;
    int n = i & (HWSZ - 1);
    int t = i >> 14;
    int k = t % KPTS; t /= KPTS;
    int g = t & 7;
    int b = t >> 3;
    int h = n >> 7, w = n & 127;

    const float* om = g_om + (size_t)b * OMCH * HWSZ;
    int gk = g * KPTS + k;
    float offy = om[(size_t)gk * HWSZ + n];
    float offx = om[(size_t)(72 + gk) * HWSZ + n];
    float mm   = om[(size_t)(144 + gk) * HWSZ + n];
    mm = 1.f / (1.f + expf(-mm));

    float py = (float)(h + k / 3 - 1) + offy;
    float px = (float)(w + k % 3 - 1) + offx;
    float y0f = floorf(py), x0f = floorf(px);
    float ly = py - y0f, lx = px - x0f;
    int y0 = (int)y0f, x0 = (int)x0f;
    int y1 = y0 + 1, x1 = x0 + 1;
    bool vy0 = (y0 >= 0 && y0 < 128), vy1 = (y1 >= 0 && y1 < 128);
    bool vx0 = (x0 >= 0 && x0 < 128), vx1 = (x1 >= 0 && x1 < 128);
    int cy0 = min(max(y0, 0), 127), cy1 = min(max(y1, 0), 127);
    int cx0 = min(max(x0, 0), 127), cx1 = min(max(x1, 0), 127);
    float w00 = (vy0 && vx0) ? (1.f - ly) * (1.f - lx) * mm : 0.f;
    float w01 = (vy0 && vx1) ? (1.f - ly) * lx * mm : 0.f;
    float w10 = (vy1 && vx0) ? ly * (1.f - lx) * mm : 0.f;
    float w11 = (vy1 && vx1) ? ly * lx * mm : 0.f;
    int i00 = (cy0 << 7) + cx0, i01 = (cy0 << 7) + cx1;
    int i10 = (cy1 << 7) + cx0, i11 = (cy1 << 7) + cx1;

    const unsigned int* cw = g_upw + (size_t)b * (CC / 2) * HWSZ;
    __half* Sb = g_Sh2 + (size_t)b * KBIG * HWSZ;
    #pragma unroll
    for (int cp = 0; cp < 8; cp++) {
        const unsigned int* rowp = cw + (size_t)(g * 8 + cp) * HWSZ;
        float2 c00 = __half22float2(*(const __half2*)&rowp[i00]);
        float2 c01 = __half22float2(*(const __half2*)&rowp[i01]);
        float2 c10 = __half22float2(*(const __half2*)&rowp[i10]);
        float2 c11 = __half22float2(*(const __half2*)&rowp[i11]);
        float ve = w00 * c00.x + w01 * c01.x + w10 * c10.x + w11 * c11.x;
        float vo = w00 * c00.y + w01 * c01.y + w10 * c10.y + w11 * c11.y;
        int re = g * 144 + (2 * cp) * 9 + k;
        Sb[(size_t)re * HWSZ + n] = __float2half(ve);
        Sb[(size_t)(re + 9) * HWSZ + n] = __float2half(vo);
    }
}

// ---------------- FP16 tensor-core GEMM (unified) ----------------
// BM=128, BN=128, BK=32, 256 thr, 8 warps 2x4. A frags: ldmatrix.x4.
// B smem: plain k-major [32 k][136 halves] per stage; B frags: ldmatrix.x2.trans.
// BSRC 0: B = plain global rows Bh[k][n]; BSRC 1: rows from shifted off_feat copies.
// EPI 0: bias; 2: relu+bias+Add; 3: fp32 C + plain fp16 Ch; 6: 3 shifted copies.
#define AHSTR 40
#define BROWH 136                 // halves per B smem k-row (272B; conflict-free LDSM)
#define A_STG (128 * AHSTR)       // halves
#define B_STGH (32 * BROWH)       // halves
#define SMEM_BYTES (3 * (A_STG + B_STGH) * 2)   // 56832

template<int EPI, int ARMW, int BSRC, int MT>
__global__ __launch_bounds__(256, 2) void hgemm(
    const __half* __restrict__ A, int lda,
    const __half* __restrict__ Bh, size_t sB,
    const float* __restrict__ bias,
    float* __restrict__ C, size_t sC,
    __half* __restrict__ Ch, size_t sCh,
    const float* __restrict__ Add, size_t sAdd,
    const float* __restrict__ Scl,
    int bmofs, int M, int K, int N)
{
    const int bz = blockIdx.z;
    Bh += (size_t)bz * sB;

    extern __shared__ __align__(16) char dsmem[];
    __half* Asm = (__half*)dsmem;
    __half* Bsm = (__half*)(dsmem + 3 * A_STG * 2);

    const int tid = threadIdx.x, lane = tid & 31, warp = tid >> 5;
    const int gid = lane >> 2, tig = lane & 3;
    const int wm = (warp >> 2) * (MT * 16), wn = (warp & 3) * 32;
    const int bm = bmofs, bn = blockIdx.x * 128;
    const int hrow = blockIdx.x;     // image row for BSRC=1

    const int arow = tid >> 1, ac = (tid & 1) * 16;
    const __half* Ap = A + (size_t)(bm + arow) * lda + ac;
    const int apred = ((bm + arow) < M) ? 16 : 0;
    const int br = tid >> 3, bc = (tid & 7) * 16;   // B loader: k-row, half-chunk

    float acc[MT][4][4];
    #pragma unroll
    for (int mi = 0; mi < MT; mi++)
        #pragma unroll
        for (int ni = 0; ni < 4; ni++)
            #pragma unroll
            for (int q = 0; q < 4; q++) acc[mi][ni][q] = 0.f;

    const int nk = K >> 5;

    auto stage = [&](int kb, int buf) {
        // A
        if (ARMW) {
            const float* gw = (const float*)A + (size_t)(bm + arow) * lda + kb * 32 + ac;
            const float* sc = Scl + bz * CC + kb * 32 + ac;
            __half hv[16];
            #pragma unroll
            for (int j = 0; j < 16; j += 4) {
                float4 w4 = *(const float4*)(gw + j);
                hv[j + 0] = __float2half(w4.x * sc[j + 0]);
                hv[j + 1] = __float2half(w4.y * sc[j + 1]);
                hv[j + 2] = __float2half(w4.z * sc[j + 2]);
                hv[j + 3] = __float2half(w4.w * sc[j + 3]);
            }
            __half* d = Asm + (size_t)buf * A_STG + arow * AHSTR + ac;
            *(uint4*)d = *(uint4*)hv;
            *(uint4*)(d + 8) = *(uint4*)(hv + 8);
        } else {
            unsigned int sa = (unsigned int)__cvta_generic_to_shared(Asm + (size_t)buf * A_STG + arow * AHSTR + ac);
            const __half* ga = Ap + kb * 32;
            asm volatile("cp.async.ca.shared.global [%0], [%1], 16, %2;\n" :: "r"(sa), "l"(ga), "r"(apred));
            asm volatile("cp.async.ca.shared.global [%0], [%1], 16, %2;\n" :: "r"(sa + 16), "l"(ga + 8), "r"(apred));
        }
        // B
        unsigned int sb = (unsigned int)__cvta_generic_to_shared(Bsm + (size_t)buf * B_STGH + br * BROWH + bc);
        if (BSRC == 0) {
            const __half* gb = Bh + (size_t)(kb * 32 + br) * N + bn + bc;
            asm volatile("cp.async.cg.shared.global [%0], [%1], 16;\n" :: "r"(sb), "l"(gb));
            asm volatile("cp.async.cg.shared.global [%0], [%1], 16;\n" :: "r"(sb + 16), "l"(gb + 8));
        } else {
            int ck = kb * 32 + br;
            int c  = ck / 9;
            int kk = ck - 9 * c;
            int dy = kk / 3 - 1;
            int ci = kk - (kk / 3) * 3;
            int hs = hrow + dy;
            int p = ((unsigned)hs < 128u) ? 16 : 0;
            const __half* gb = g_offh3 + (((size_t)ci * BATCH + bz) * CC + c) * HWSZ + hs * 128 + bc;
            asm volatile("cp.async.cg.shared.global [%0], [%1], 16, %2;\n" :: "r"(sb), "l"(gb), "r"(p));
            asm volatile("cp.async.cg.shared.global [%0], [%1], 16, %2;\n" :: "r"(sb + 16), "l"(gb + 8), "r"(p));
        }
        asm volatile("cp.async.commit_group;\n");
    };

    stage(0, 0);
    if (nk > 1) stage(1, 1);
    if (ARMW) __syncthreads();
    for (int kb = 0; kb < nk; kb++) {
        const int cur = kb % 3;
        if (kb + 1 < nk) { asm volatile("cp.async.wait_group 1;\n"); }
        else             { asm volatile("cp.async.wait_group 0;\n"); }
        __syncthreads();
        if (kb + 2 < nk) stage(kb + 2, (kb + 2) % 3);
        {
            const unsigned int abase = (unsigned int)__cvta_generic_to_shared(Asm + (size_t)cur * A_STG);
            const unsigned int bbase = (unsigned int)__cvta_generic_to_shared(Bsm + (size_t)cur * B_STGH);
            const int l15 = lane & 15, lhi8 = (lane >> 4) * 8;
            #pragma unroll
            for (int ks = 0; ks < 2; ks++) {
                unsigned int af[MT][4], bf[4][2];
                #pragma unroll
                for (int mi = 0; mi < MT; mi++) {
                    unsigned int aaddr = abase +
                        ((unsigned int)((wm + mi * 16 + l15) * AHSTR + ks * 16 + lhi8) << 1);
                    asm volatile(
                        "ldmatrix.sync.aligned.m8n8.x4.shared.b16 {%0,%1,%2,%3}, [%4];\n"
                        : "=r"(af[mi][0]), "=r"(af[mi][1]), "=r"(af[mi][2]), "=r"(af[mi][3])
                        : "r"(aaddr));
                }
                #pragma unroll
                for (int ni = 0; ni < 4; ni++) {
                    unsigned int baddr = bbase +
                        ((unsigned int)((ks * 16 + l15) * BROWH + wn + ni * 8) << 1);
                    asm volatile(
                        "ldmatrix.sync.aligned.m8n8.x2.trans.shared.b16 {%0,%1}, [%2];\n"
                        : "=r"(bf[ni][0]), "=r"(bf[ni][1])
                        : "r"(baddr));
                }
                #pragma unroll
                for (int mi = 0; mi < MT; mi++)
                    #pragma unroll
                    for (int ni = 0; ni < 4; ni++) {
                        asm volatile(
                            "mma.sync.aligned.m16n8k16.row.col.f32.f16.f16.f32 "
                            "{%0,%1,%2,%3}, {%4,%5,%6,%7}, {%8,%9}, {%0,%1,%2,%3};\n"
                            : "+f"(acc[mi][ni][0]), "+f"(acc[mi][ni][1]),
                              "+f"(acc[mi][ni][2]), "+f"(acc[mi][ni][3])
                            : "r"(af[mi][0]), "r"(af[mi][1]), "r"(af[mi][2]), "r"(af[mi][3]),
                              "r"(bf[ni][0]), "r"(bf[ni][1]));
                    }
            }
        }
    }

    #pragma unroll
    for (int mi = 0; mi < MT; mi++) {
        const int r0 = bm + wm + mi * 16 + gid;
        const int r1 = r0 + 8;
        const bool ok0 = r0 < M, ok1 = r1 < M;
        const float bv0 = (bias && ok0) ? bias[r0] : 0.f;
        const float bv1 = (bias && ok1) ? bias[r1] : 0.f;
        #pragma unroll
        for (int ni = 0; ni < 4; ni++) {
            const int cc = bn + wn + ni * 8 + 2 * tig;
            #pragma unroll
            for (int hm = 0; hm < 2; hm++) {
                const int r = hm ? r1 : r0;
                if (!(hm ? ok1 : ok0)) continue;
                float v0 = acc[mi][ni][hm * 2 + 0] + (hm ? bv1 : bv0);
                float v1 = acc[mi][ni][hm * 2 + 1] + (hm ? bv1 : bv0);
                if (EPI == 0) {
                    size_t o = (size_t)bz * sC + (size_t)r * N + cc;
                    *(float2*)&C[o] = make_float2(v0, v1);
                } else if (EPI == 2) {
                    size_t o = (size_t)bz * sC + (size_t)r * N + cc;
                    const float2 ad = *(const float2*)&Add[(size_t)bz * sAdd + (size_t)r * N + cc];
                    C[o] = fmaxf(v0, 0.f) + ad.x;
                    C[o + 1] = fmaxf(v1, 0.f) + ad.y;
                } else if (EPI == 3) {
                    size_t o = (size_t)bz * sC + (size_t)r * N + cc;
                    *(float2*)&C[o] = make_float2(v0, v1);
                    size_t oh = (size_t)bz * sCh + (size_t)r * N + cc;
                    *(__half2*)&Ch[oh] = __halves2half2(__float2half(v0), __float2half(v1));
                } else if (EPI == 6) {
                    const int w = cc & 127;
                    const __half h0 = __float2half(v0), h1 = __float2half(v1);
                    const size_t rowoff = (size_t)r * HWSZ + (size_t)(cc & ~127);
                    __half* c0 = g_offh3 + ((size_t)0 * BATCH + bz) * CC * HWSZ + rowoff;
                    __half* c1 = g_offh3 + ((size_t)1 * BATCH + bz) * CC * HWSZ + rowoff;
                    __half* c2 = g_offh3 + ((size_t)2 * BATCH + bz) * CC * HWSZ + rowoff;
                    *(__half2*)&c1[w] = __halves2half2(h0, h1);
                    c0[w + 1] = h0;
                    if (w + 2 < 128) c0[w + 2] = h1;
                    if (w > 0) c2[w - 1] = h0;
                    c2[w] = h1;
                }
            }
        }
    }
}

// ---------------- launch ----------------
extern "C" void kernel_launch(void* const* d_in, const int* in_sizes, int n_in,
                              void* d_out, int out_size) {
    const float* feat_l  = (const float*)d_in[0];
    const float* feat_s  = (const float*)d_in[1];
    const float* atten_w = (const float*)d_in[2];
    const float* atten_b = (const float*)d_in[3];
    const float* bn_g    = (const float*)d_in[4];
    const float* bn_b    = (const float*)d_in[5];
    const float* bn_m    = (const float*)d_in[6];
    const float* bn_v    = (const float*)d_in[7];
    const float* fsm_w   = (const float*)d_in[8];
    const float* fsm_b   = (const float*)d_in[9];
    const float* om_b    = (const float*)d_in[12];
    const float* dcn_b   = (const float*)d_in[14];
    float* out = (float*)d_out;

    float *p_cat, *p_om, *p_scale;
    __half *p_offwh, *p_dcnwh, *p_omwh, *p_flh, *p_cath, *p_Sh2;
    cudaGetSymbolAddress((void**)&p_cat,   g_cat);
    cudaGetSymbolAddress((void**)&p_om,    g_om);
    cudaGetSymbolAddress((void**)&p_scale, g_scale);
    cudaGetSymbolAddress((void**)&p_offwh, g_offwh);
    cudaGetSymbolAddress((void**)&p_dcnwh, g_dcnwh);
    cudaGetSymbolAddress((void**)&p_omwh,  g_omwh);
    cudaGetSymbolAddress((void**)&p_flh,   g_flh);
    cudaGetSymbolAddress((void**)&p_cath,  g_cath);
    cudaGetSymbolAddress((void**)&p_Sh2,   g_Sh2);

    cudaFuncSetAttribute(hgemm<3,1,0,4>, cudaFuncAttributeMaxDynamicSharedMemorySize, SMEM_BYTES);
    cudaFuncSetAttribute(hgemm<6,0,0,4>, cudaFuncAttributeMaxDynamicSharedMemorySize, SMEM_BYTES);
    cudaFuncSetAttribute(hgemm<0,0,1,4>, cudaFuncAttributeMaxDynamicSharedMemorySize, SMEM_BYTES);
    cudaFuncSetAttribute(hgemm<0,0,1,3>, cudaFuncAttributeMaxDynamicSharedMemorySize, SMEM_BYTES);
    cudaFuncSetAttribute(hgemm<2,0,0,4>, cudaFuncAttributeMaxDynamicSharedMemorySize, SMEM_BYTES);

    // 1) prep (+whpack +edge zero), SE gate
    prep3_kernel<<<(BATCH * (CC / 2) * HWSZ + 255) / 256, 256>>>(
        feat_l, feat_s,
        (const float*)d_in[11], (const float*)d_in[13], (const float*)d_in[10]);
    pool_kernel<<<BATCH * CC, 256>>>(feat_l);
    atten_kernel<<<1, 256>>>(atten_w, atten_b, bn_g, bn_b, bn_m, bn_v);

    // 2) feat_arm GEMM (A built in-loader) -> fp32 g_cat + plain fp16 g_cath rows 0..127
    hgemm<3,1,0,4><<<dim3(128, 1, BATCH), 256, SMEM_BYTES>>>(
        (const __half*)fsm_w, CC,
        p_flh, (size_t)CC * HWSZ,
        fsm_b,
        p_cat, (size_t)2 * CC * HWSZ,
        p_cath, (size_t)2 * CC * HWSZ,
        nullptr, 0,
        p_scale,
        0, CC, CC, HWSZ);

    // 3) off_feat GEMM (B = g_cath rows 0..255) -> 3 shifted fp16 copies
    hgemm<6,0,0,4><<<dim3(128, 1, BATCH), 256, SMEM_BYTES>>>(
        p_offwh, 2 * CC,
        p_cath, (size_t)2 * CC * HWSZ,
        nullptr,
        nullptr, 0,
        nullptr, 0,
        nullptr, 0,
        nullptr,
        0, CC, 2 * CC, HWSZ);

    // 4) fused im2col + 3x3 conv (pure cp.async B from shifted copies)
    hgemm<0,0,1,4><<<dim3(128, 1, BATCH), 256, SMEM_BYTES>>>(
        p_omwh, KBIG,
        nullptr, 0,
        om_b,
        p_om, (size_t)OMCH * HWSZ,
        nullptr, 0,
        nullptr, 0,
        nullptr,
        0, OMCH, KBIG, HWSZ);
    hgemm<0,0,1,3><<<dim3(128, 1, BATCH), 256, SMEM_BYTES>>>(
        p_omwh, KBIG,
        nullptr, 0,
        om_b,
        p_om, (size_t)OMCH * HWSZ,
        nullptr, 0,
        nullptr, 0,
        nullptr,
        128, OMCH, KBIG, HWSZ);

    // 5) bilinear sample + mask -> plain fp16 g_Sh2
    sample_kernel<<<(BATCH * DGRP * KPTS * HWSZ + 255) / 256, 256>>>();

    // 6) DCN GEMM (pure cp.async B from g_Sh2) + relu + bias + feat_arm -> out
    hgemm<2,0,0,4><<<dim3(128, 1, BATCH), 256, SMEM_BYTES>>>(
        p_dcnwh, KBIG,
        p_Sh2, (size_t)KBIG * HWSZ,
        dcn_b,
        out, (size_t)CC * HWSZ,
        nullptr, 0,
        p_cat, (size_t)2 * CC * HWSZ,
        nullptr,
        0, CC, KBIG, HWSZ);
}